// round 12
// baseline (speedup 1.0000x reference)
#include <cuda_runtime.h>
#include <cuda_bf16.h>
#include <math.h>
#include <stdint.h>

#define B_   64
#define T_   256
#define D_   512
#define U_   512
#define G3   1536   // 3*U
#define V_   32000
#define GHC  4      // partial k-chunks for recurrence (one per kc block)

typedef unsigned long long ull;

// ---------------- device scratch (static: no runtime allocation) ----------
__device__ float g_GX[2][T_][B_][G3];      // e@W + b_in, per direction
__device__ float g_GHp[GHC][2][B_][G3];    // k-chunk partial sums of h@Uw
__device__ float g_H[2][B_][U_];           // hidden state
__device__ float g_embr[(size_t)V_ * D_];  // tf32-rounded embedding
__device__ float g_Wr[2][D_ * G3];         // tf32-rounded W (fwd/bwd)

// per-(dir,bt) barrier state, padded to separate cache lines
struct __align__(128) BarState { unsigned int count; unsigned int gen; unsigned int pad[30]; };
__device__ BarState g_bar[4];

// ---------------- helpers --------------------------------------------------
__device__ __forceinline__ float to_tf32(float v) {
    uint32_t u;
    asm("cvt.rna.tf32.f32 %0, %1;" : "=r"(u) : "f"(v));
    return __uint_as_float(u);
}
__device__ __forceinline__ void mma_bf16(float* c, const uint32_t* a, uint32_t b0, uint32_t b1) {
    asm volatile(
        "mma.sync.aligned.m16n8k16.row.col.f32.bf16.bf16.f32 "
        "{%0,%1,%2,%3}, {%4,%5,%6,%7}, {%8,%9}, {%0,%1,%2,%3};"
        : "+f"(c[0]), "+f"(c[1]), "+f"(c[2]), "+f"(c[3])
        : "r"(a[0]), "r"(a[1]), "r"(a[2]), "r"(a[3]), "r"(b0), "r"(b1));
}

// ---------------- software barrier over one (dir,bt) group's 32 blocks ----
// Same proven logic as R2/R11; smaller domain, pure volatile spin (no sleep).
__device__ __forceinline__ void grp_sync(int grp, unsigned nb) {
    volatile unsigned* vgen = (volatile unsigned*)&g_bar[grp].gen;
    __syncthreads();
    if (threadIdx.x == 0) {
        unsigned gen = *vgen;
        __threadfence();                       // order gen-read & prior stores before arrive
        if (atomicAdd(&g_bar[grp].count, 1u) == nb - 1u) {
            g_bar[grp].count = 0u;
            __threadfence();
            atomicAdd(&g_bar[grp].gen, 1u);
        } else {
            while (*vgen == gen) { }
        }
        __threadfence();                       // acquire
    }
    __syncthreads();
}

// ======================================================================
// Kernel 0: round emb / Wf / Wb to tf32 (rna) into static buffers.
// ======================================================================
__global__ __launch_bounds__(256)
void k_round(const float* __restrict__ emb,
             const float* __restrict__ Wf,
             const float* __restrict__ Wb)
{
    const size_t stride = (size_t)gridDim.x * blockDim.x;
    const size_t i0 = (size_t)blockIdx.x * blockDim.x + threadIdx.x;
    const size_t n_emb4 = (size_t)V_ * D_ / 4;
    const size_t n_w4   = (size_t)D_ * G3 / 4;

    for (size_t i = i0; i < n_emb4; i += stride) {
        float4 v = ((const float4*)emb)[i];
        v.x = to_tf32(v.x); v.y = to_tf32(v.y); v.z = to_tf32(v.z); v.w = to_tf32(v.w);
        ((float4*)g_embr)[i] = v;
    }
    for (size_t i = i0; i < n_w4; i += stride) {
        float4 a = ((const float4*)Wf)[i];
        a.x = to_tf32(a.x); a.y = to_tf32(a.y); a.z = to_tf32(a.z); a.w = to_tf32(a.w);
        ((float4*)g_Wr[0])[i] = a;
        float4 b = ((const float4*)Wb)[i];
        b.x = to_tf32(b.x); b.y = to_tf32(b.y); b.z = to_tf32(b.z); b.w = to_tf32(b.w);
        ((float4*)g_Wr[1])[i] = b;
    }
}

// ======================================================================
// Kernel 1 (mma.sync tf32): GX[dir][t][b][:] = emb[x[b][t]] @ W_dir + b_in
// (unchanged from round 10/11, proven)
// ======================================================================
__global__ __launch_bounds__(256, 2)
void k_input_gemm_mma(const int* __restrict__ x,
                      const float* __restrict__ bf,
                      const float* __restrict__ bb)
{
    __shared__ float As[128 * 36];
    __shared__ float Bs[32 * 132];
    __shared__ int   tok[128];

    const int jt  = blockIdx.x;     // 0..11
    const int mt  = blockIdx.y;     // 0..127
    const int dir = blockIdx.z;
    const float* __restrict__ W   = dir ? g_Wr[1] : g_Wr[0];
    const float* __restrict__ bin = dir ? bb : bf;
    const int j0 = jt * 128;
    const int m0 = mt * 128;

    const int tid  = threadIdx.x;
    const int warp = tid >> 5;
    const int lane = tid & 31;
    const int g    = lane >> 2;
    const int tg   = lane & 3;
    const int wm0  = (warp >> 2) * 64;
    const int wn0  = (warp & 3) * 32;

    if (tid < 128) {
        int m = m0 + tid;
        tok[tid] = x[(m & 63) * T_ + (m >> 6)];
    }

    float acc[4][4][4];
#pragma unroll
    for (int mi = 0; mi < 4; ++mi)
#pragma unroll
        for (int ni = 0; ni < 4; ++ni)
#pragma unroll
            for (int q = 0; q < 4; ++q) acc[mi][ni][q] = 0.f;

    for (int kc = 0; kc < 16; ++kc) {
        const int k0 = kc * 32;
        __syncthreads();
#pragma unroll
        for (int it = 0; it < 4; ++it) {
            int idx = it * 256 + tid;
            int r   = idx >> 3;
            int q   = (idx & 7) * 4;
            float4 v = *(const float4*)&g_embr[(size_t)tok[r] * D_ + k0 + q];
            *(float4*)&As[r * 36 + q] = v;
        }
#pragma unroll
        for (int it = 0; it < 4; ++it) {
            int idx = it * 256 + tid;
            int k   = idx >> 5;
            int n4  = (idx & 31) * 4;
            float4 v = *(const float4*)&W[(size_t)(k0 + k) * G3 + j0 + n4];
            *(float4*)&Bs[k * 132 + n4] = v;
        }
        __syncthreads();

#pragma unroll
        for (int k8 = 0; k8 < 4; ++k8) {
            const int kk = k8 * 8;
            uint32_t bfr[4][2];
#pragma unroll
            for (int ni = 0; ni < 4; ++ni) {
                int n = wn0 + ni * 8 + g;
                bfr[ni][0] = __float_as_uint(Bs[(kk + tg) * 132 + n]);
                bfr[ni][1] = __float_as_uint(Bs[(kk + tg + 4) * 132 + n]);
            }
#pragma unroll
            for (int mi = 0; mi < 4; ++mi) {
                int mr = wm0 + mi * 16 + g;
                uint32_t afr[4];
                afr[0] = __float_as_uint(As[mr * 36 + kk + tg]);
                afr[1] = __float_as_uint(As[(mr + 8) * 36 + kk + tg]);
                afr[2] = __float_as_uint(As[mr * 36 + kk + tg + 4]);
                afr[3] = __float_as_uint(As[(mr + 8) * 36 + kk + tg + 4]);
#pragma unroll
                for (int ni = 0; ni < 4; ++ni) {
                    asm volatile(
                        "mma.sync.aligned.m16n8k8.row.col.f32.tf32.tf32.f32 "
                        "{%0,%1,%2,%3}, {%4,%5,%6,%7}, {%8,%9}, {%0,%1,%2,%3};"
                        : "+f"(acc[mi][ni][0]), "+f"(acc[mi][ni][1]),
                          "+f"(acc[mi][ni][2]), "+f"(acc[mi][ni][3])
                        : "r"(afr[0]), "r"(afr[1]), "r"(afr[2]), "r"(afr[3]),
                          "r"(bfr[ni][0]), "r"(bfr[ni][1]));
                }
            }
        }
    }

#pragma unroll
    for (int mi = 0; mi < 4; ++mi) {
        int m_lo = m0 + wm0 + mi * 16 + g;
        int m_hi = m_lo + 8;
#pragma unroll
        for (int ni = 0; ni < 4; ++ni) {
            int c = j0 + wn0 + ni * 8 + 2 * tg;
            float2 bi = *(const float2*)&bin[c];
            float2 v0 = make_float2(acc[mi][ni][0] + bi.x, acc[mi][ni][1] + bi.y);
            float2 v1 = make_float2(acc[mi][ni][2] + bi.x, acc[mi][ni][3] + bi.y);
            *(float2*)&g_GX[dir][m_lo >> 6][m_lo & 63][c] = v0;
            *(float2*)&g_GX[dir][m_hi >> 6][m_hi & 63][c] = v1;
        }
    }
}

// ======================================================================
// Kernel 2: persistent bidirectional GRU recurrence.
// 128 blocks = dir(2) x bt(2 of 32 batches) x ut(8 of 64 units) x kc(4 of 128 k)
// Phase A: split-bf16 (hi+lo) tensor-core mma, 3 passes (R11, proven).
// CHANGE: barriers now span only the 32-block (dir,bt) group; phase B remapped
// to bB = b0 + (bid&31) so all A<->B dependences close within the group.
// Spin loop without nanosleep.
// ======================================================================
__global__ __launch_bounds__(256, 1)
void k_recurrence(const int* __restrict__ x,
                  const float* __restrict__ Uf,
                  const float* __restrict__ Ub,
                  const float* __restrict__ bf,
                  const float* __restrict__ bb,
                  float* __restrict__ out)
{
    extern __shared__ __nv_bfloat16 smem_bf[];
    __nv_bfloat16* h_hi = smem_bf;                    // [32][136]
    __nv_bfloat16* h_lo = smem_bf + 32 * 136;         // [32][136]
    __nv_bfloat16* u_hi = smem_bf + 64 * 136;         // [192][136]
    __nv_bfloat16* u_lo = smem_bf + 64 * 136 + 192 * 136;

    const int bid = blockIdx.x;     // 0..127
    const int tid = threadIdx.x;    // 0..255
    const int kc  = bid & 3;
    const int ut  = (bid >> 2) & 7;
    const int bt  = (bid >> 5) & 1;
    const int dir = bid >> 6;
    const int b0 = bt * 32, u0 = ut * 64, k0 = kc * 128;
    const int grp = dir * 2 + bt;   // barrier group (32 blocks)
    const float* __restrict__ Uw = dir ? Ub : Uf;

    // one-time: U slice -> bf16 hi/lo, rows o = gate*64 + unit-local (192 x 128)
    for (int v = tid; v < 192 * 128; v += 256) {
        int o = v >> 7;
        int k = v & 127;
        int gate = o >> 6, ul = o & 63;
        float w = Uw[(size_t)(k0 + k) * G3 + gate * 512 + u0 + ul];
        __nv_bfloat16 wh = __float2bfloat16(w);
        u_hi[o * 136 + k] = wh;
        u_lo[o * 136 + k] = __float2bfloat16(w - __bfloat162float(wh));
    }

    // init H = 0
    if (ut == 0) {
        for (int j = tid; j < 32 * 128; j += 256) {
            int b = j >> 7, k = j & 127;
            g_H[dir][b0 + b][k0 + k] = 0.f;
        }
    }
    grp_sync(grp, 32);

    // phase-A warp tiling: warp -> m-tile (warp&1)*16, n-base (warp>>1)*48
    const int warp  = tid >> 5;
    const int lane  = tid & 31;
    const int g     = lane >> 2;
    const int tg    = lane & 3;
    const int mrow  = (warp & 1) * 16;
    const int nbase = (warp >> 1) * 48;

    // phase-B constants (group mapping: block owns batch bB within its bt tile)
    const int bB = b0 + (bid & 31);
    const float* __restrict__ brr = (dir ? bb : bf) + G3;
    const float2 bz  = *(const float2*)&brr[2 * tid];
    const float2 brc = *(const float2*)&brr[512 + 2 * tid];
    const float2 bhc = *(const float2*)&brr[1024 + 2 * tid];

    float* __restrict__ state = out + (size_t)B_ * T_ * 1024;

    for (int s = 0; s < T_; ++s) {
        // ---- stage h: global fp32 -> smem bf16 hi/lo ----------------------
        for (int j4 = tid; j4 < 1024; j4 += 256) {
            int b  = j4 >> 5;
            int kv = (j4 & 31) * 4;
            float4 v = __ldcg((const float4*)&g_H[dir][b0 + b][k0 + kv]);
            int base = b * 136 + kv;
            __nv_bfloat16 t0 = __float2bfloat16(v.x);
            __nv_bfloat16 t1 = __float2bfloat16(v.y);
            __nv_bfloat16 t2 = __float2bfloat16(v.z);
            __nv_bfloat16 t3 = __float2bfloat16(v.w);
            h_hi[base + 0] = t0; h_hi[base + 1] = t1;
            h_hi[base + 2] = t2; h_hi[base + 3] = t3;
            h_lo[base + 0] = __float2bfloat16(v.x - __bfloat162float(t0));
            h_lo[base + 1] = __float2bfloat16(v.y - __bfloat162float(t1));
            h_lo[base + 2] = __float2bfloat16(v.z - __bfloat162float(t2));
            h_lo[base + 3] = __float2bfloat16(v.w - __bfloat162float(t3));
        }
        __syncthreads();

        // ---- phase A: gh partial = h @ Uw via split-bf16 mma (3 passes) ---
        float acc[6][4];
#pragma unroll
        for (int ni = 0; ni < 6; ++ni)
#pragma unroll
            for (int q = 0; q < 4; ++q) acc[ni][q] = 0.f;

#pragma unroll
        for (int k8 = 0; k8 < 8; ++k8) {
            const int kk = k8 * 16 + 2 * tg;
            uint32_t ah[4], al[4];
            ah[0] = *(const uint32_t*)&h_hi[(mrow + g) * 136 + kk];
            ah[1] = *(const uint32_t*)&h_hi[(mrow + g + 8) * 136 + kk];
            ah[2] = *(const uint32_t*)&h_hi[(mrow + g) * 136 + kk + 8];
            ah[3] = *(const uint32_t*)&h_hi[(mrow + g + 8) * 136 + kk + 8];
            al[0] = *(const uint32_t*)&h_lo[(mrow + g) * 136 + kk];
            al[1] = *(const uint32_t*)&h_lo[(mrow + g + 8) * 136 + kk];
            al[2] = *(const uint32_t*)&h_lo[(mrow + g) * 136 + kk + 8];
            al[3] = *(const uint32_t*)&h_lo[(mrow + g + 8) * 136 + kk + 8];
#pragma unroll
            for (int ni = 0; ni < 6; ++ni) {
                const int orow = nbase + ni * 8 + g;
                uint32_t bh0 = *(const uint32_t*)&u_hi[orow * 136 + kk];
                uint32_t bh1 = *(const uint32_t*)&u_hi[orow * 136 + kk + 8];
                uint32_t bl0 = *(const uint32_t*)&u_lo[orow * 136 + kk];
                uint32_t bl1 = *(const uint32_t*)&u_lo[orow * 136 + kk + 8];
                mma_bf16(acc[ni], ah, bh0, bh1);
                mma_bf16(acc[ni], al, bh0, bh1);
                mma_bf16(acc[ni], ah, bl0, bl1);
            }
        }

        // store partials: c0,c1 -> row (mrow+g), c2,c3 -> row (mrow+g+8)
#pragma unroll
        for (int ni = 0; ni < 6; ++ni) {
            int o = nbase + ni * 8 + 2 * tg;
            int gate = o >> 6, ul = o & 63;
            int col = gate * 512 + u0 + ul;
            int r0 = b0 + mrow + g;
            __stcg((float2*)&g_GHp[kc][dir][r0][col],     make_float2(acc[ni][0], acc[ni][1]));
            __stcg((float2*)&g_GHp[kc][dir][r0 + 8][col], make_float2(acc[ni][2], acc[ni][3]));
        }
        grp_sync(grp, 32);

        // ---- phase B: gates + state update + output (own bt tile) --------
        {
            const int t = dir ? (T_ - 1 - s) : s;
            const bool m = (x[bB * T_ + t] != 0);
            const int u = 2 * tid;

            float2 gz = bz, gr = brc, gh = bhc;
#pragma unroll
            for (int c = 0; c < GHC; ++c) {
                float2 a  = __ldcg((const float2*)&g_GHp[c][dir][bB][u]);
                float2 b2 = __ldcg((const float2*)&g_GHp[c][dir][bB][512 + u]);
                float2 c2 = __ldcg((const float2*)&g_GHp[c][dir][bB][1024 + u]);
                gz.x += a.x;  gz.y += a.y;
                gr.x += b2.x; gr.y += b2.y;
                gh.x += c2.x; gh.y += c2.y;
            }
            const float* __restrict__ gx = &g_GX[dir][t][bB][0];
            float2 xz = *(const float2*)&gx[u];
            float2 xr = *(const float2*)&gx[512 + u];
            float2 xh = *(const float2*)&gx[1024 + u];
            float2 hold = __ldcg((const float2*)&g_H[dir][bB][u]);

            float2 hn;
            {
                float z  = __fdividef(1.f, 1.f + __expf(-(xz.x + gz.x)));
                float rr = __fdividef(1.f, 1.f + __expf(-(xr.x + gr.x)));
                float a  = xh.x + rr * gh.x;
                float hc = 1.f - __fdividef(2.f, 1.f + __expf(2.f * a));
                hn.x = z * hold.x + (1.f - z) * hc;
                hn.x = m ? hn.x : hold.x;
            }
            {
                float z  = __fdividef(1.f, 1.f + __expf(-(xz.y + gz.y)));
                float rr = __fdividef(1.f, 1.f + __expf(-(xr.y + gr.y)));
                float a  = xh.y + rr * gh.y;
                float hc = 1.f - __fdividef(2.f, 1.f + __expf(2.f * a));
                hn.y = z * hold.y + (1.f - z) * hc;
                hn.y = m ? hn.y : hold.y;
            }

            __stcg((float2*)&g_H[dir][bB][u], hn);
            *(float2*)&out[((size_t)bB * T_ + t) * 1024 + dir * 512 + u] = hn;
            if (s == T_ - 1)
                *(float2*)&state[(size_t)bB * 1024 + dir * 512 + u] = hn;
        }
        grp_sync(grp, 32);
    }
}

// ======================================================================
// Kernel 3: LayerNorm over last dim (1024) of out, in place
// ======================================================================
__global__ __launch_bounds__(256)
void k_layernorm(float* __restrict__ out,
                 const float* __restrict__ gamma,
                 const float* __restrict__ beta)
{
    const int row = blockIdx.x;
    float* p = out + (size_t)row * 1024;
    const int tid = threadIdx.x;

    float4 v = *(const float4*)&p[tid * 4];
    float s = v.x + v.y + v.z + v.w;
    float q = v.x * v.x + v.y * v.y + v.z * v.z + v.w * v.w;
#pragma unroll
    for (int o = 16; o; o >>= 1) {
        s += __shfl_xor_sync(0xFFFFFFFFu, s, o);
        q += __shfl_xor_sync(0xFFFFFFFFu, q, o);
    }
    __shared__ float ss[8], qq[8];
    __shared__ float mean_s, rstd_s;
    if ((tid & 31) == 0) { ss[tid >> 5] = s; qq[tid >> 5] = q; }
    __syncthreads();
    if (tid == 0) {
        float S = 0.f, Q = 0.f;
#pragma unroll
        for (int i = 0; i < 8; ++i) { S += ss[i]; Q += qq[i]; }
        float mean = S * (1.f / 1024.f);
        float var  = Q * (1.f / 1024.f) - mean * mean;
        mean_s = mean;
        rstd_s = rsqrtf(var + 1e-3f);
    }
    __syncthreads();
    float mean = mean_s, rstd = rstd_s;
    float4 g  = *(const float4*)&gamma[tid * 4];
    float4 be = *(const float4*)&beta[tid * 4];
    v.x = (v.x - mean) * rstd * g.x + be.x;
    v.y = (v.y - mean) * rstd * g.y + be.y;
    v.z = (v.z - mean) * rstd * g.z + be.z;
    v.w = (v.w - mean) * rstd * g.w + be.w;
    *(float4*)&p[tid * 4] = v;
}

// ======================================================================
extern "C" void kernel_launch(void* const* d_in, const int* in_sizes, int n_in,
                              void* d_out, int out_size)
{
    const int*   x     = (const int*)  d_in[0];
    const float* emb   = (const float*)d_in[1];
    const float* Wf    = (const float*)d_in[2];
    const float* Uf    = (const float*)d_in[3];
    const float* bf    = (const float*)d_in[4];
    const float* Wb    = (const float*)d_in[5];
    const float* Ub    = (const float*)d_in[6];
    const float* bb    = (const float*)d_in[7];
    const float* gamma = (const float*)d_in[8];
    const float* beta  = (const float*)d_in[9];
    float* out = (float*)d_out;

    // smem: (h_hi+h_lo: 64 rows + u_hi+u_lo: 384 rows) x 136 bf16
    const int smem2 = (64 + 384) * 136 * 2;   // 121856 B
    cudaFuncSetAttribute(k_recurrence, cudaFuncAttributeMaxDynamicSharedMemorySize, smem2);

    k_round<<<1024, 256>>>(emb, Wf, Wb);
    dim3 g1(G3 / 128, (T_ * B_) / 128, 2);
    k_input_gemm_mma<<<g1, 256>>>(x, bf, bb);
    k_recurrence<<<128, 256, smem2>>>(x, Uf, Ub, bf, bb, out);
    k_layernorm<<<B_ * T_, 256>>>(out, gamma, beta);
}

// round 14
// speedup vs baseline: 1.0458x; 1.0458x over previous
#include <cuda_runtime.h>
#include <cuda_bf16.h>
#include <math.h>
#include <stdint.h>

#define B_   64
#define T_   256
#define D_   512
#define U_   512
#define G3   1536   // 3*U
#define V_   32000
#define GHC  4      // partial k-chunks for recurrence (one per kc block)

typedef unsigned long long ull;

// ---------------- device scratch (static: no runtime allocation) ----------
__device__ float g_GX[2][T_][B_][G3];      // e@W + b_in, per direction
__device__ float g_GHp[GHC][2][B_][G3];    // k-chunk partial sums of h@Uw
__device__ float g_H[2][B_][U_];           // hidden state
__device__ float g_embr[(size_t)V_ * D_];  // tf32-rounded embedding
__device__ float g_Wr[2][D_ * G3];         // tf32-rounded W (fwd/bwd)

// per-(dir,bt) barrier state, padded to separate cache lines
struct __align__(128) BarState { unsigned int count; unsigned int gen; unsigned int pad[30]; };
__device__ BarState g_bar[4];

// ---------------- helpers --------------------------------------------------
__device__ __forceinline__ float to_tf32(float v) {
    uint32_t u;
    asm("cvt.rna.tf32.f32 %0, %1;" : "=r"(u) : "f"(v));
    return __uint_as_float(u);
}
__device__ __forceinline__ void mma_bf16(float* c, const uint32_t* a, uint32_t b0, uint32_t b1) {
    asm volatile(
        "mma.sync.aligned.m16n8k16.row.col.f32.bf16.bf16.f32 "
        "{%0,%1,%2,%3}, {%4,%5,%6,%7}, {%8,%9}, {%0,%1,%2,%3};"
        : "+f"(c[0]), "+f"(c[1]), "+f"(c[2]), "+f"(c[3])
        : "r"(a[0]), "r"(a[1]), "r"(a[2]), "r"(a[3]), "r"(b0), "r"(b1));
}
__device__ __forceinline__ uint32_t smem_u32(const void* p) {
    uint32_t a;
    asm("{ .reg .u64 t; cvta.to.shared.u64 t, %1; cvt.u32.u64 %0, t; }" : "=r"(a) : "l"(p));
    return a;
}
#define CP_ASYNC16(dst_u32, src) \
    asm volatile("cp.async.cg.shared.global [%0], [%1], 16;" :: "r"(dst_u32), "l"(src))
#define CP_COMMIT() asm volatile("cp.async.commit_group;" ::: "memory")
#define CP_WAIT(n)  asm volatile("cp.async.wait_group %0;" :: "n"(n) : "memory")

// ---------------- software barrier over one (dir,bt) group's 32 blocks ----
__device__ __forceinline__ void grp_sync(int grp, unsigned nb) {
    volatile unsigned* vgen = (volatile unsigned*)&g_bar[grp].gen;
    __syncthreads();
    if (threadIdx.x == 0) {
        unsigned gen = *vgen;
        __threadfence();                       // order gen-read & prior stores before arrive
        if (atomicAdd(&g_bar[grp].count, 1u) == nb - 1u) {
            g_bar[grp].count = 0u;
            __threadfence();
            atomicAdd(&g_bar[grp].gen, 1u);
        } else {
            while (*vgen == gen) { }
        }
        __threadfence();                       // acquire
    }
    __syncthreads();
}

// ======================================================================
// Kernel 0: round emb / Wf / Wb to tf32 (rna) into static buffers.
// ======================================================================
__global__ __launch_bounds__(256)
void k_round(const float* __restrict__ emb,
             const float* __restrict__ Wf,
             const float* __restrict__ Wb)
{
    const size_t stride = (size_t)gridDim.x * blockDim.x;
    const size_t i0 = (size_t)blockIdx.x * blockDim.x + threadIdx.x;
    const size_t n_emb4 = (size_t)V_ * D_ / 4;
    const size_t n_w4   = (size_t)D_ * G3 / 4;

    for (size_t i = i0; i < n_emb4; i += stride) {
        float4 v = ((const float4*)emb)[i];
        v.x = to_tf32(v.x); v.y = to_tf32(v.y); v.z = to_tf32(v.z); v.w = to_tf32(v.w);
        ((float4*)g_embr)[i] = v;
    }
    for (size_t i = i0; i < n_w4; i += stride) {
        float4 a = ((const float4*)Wf)[i];
        a.x = to_tf32(a.x); a.y = to_tf32(a.y); a.z = to_tf32(a.z); a.w = to_tf32(a.w);
        ((float4*)g_Wr[0])[i] = a;
        float4 b = ((const float4*)Wb)[i];
        b.x = to_tf32(b.x); b.y = to_tf32(b.y); b.z = to_tf32(b.z); b.w = to_tf32(b.w);
        ((float4*)g_Wr[1])[i] = b;
    }
}

// ======================================================================
// Kernel 1 (mma.sync tf32, cp.async double-buffered):
// GX[dir][t][b][:] = emb[x[b][t]] @ W_dir + b_in
// Block tile 128x128, BK=32; A smem [m][k] stride 36; B smem [k][n] stride 132.
// ======================================================================
__global__ __launch_bounds__(256, 2)
void k_input_gemm_mma(const int* __restrict__ x,
                      const float* __restrict__ bf,
                      const float* __restrict__ bb)
{
    extern __shared__ float smem_k1[];
    // layout: As0[4608] As1[4608] Bs0[4224] Bs1[4224]
    float* Asb[2] = { smem_k1, smem_k1 + 4608 };
    float* Bsb[2] = { smem_k1 + 9216, smem_k1 + 9216 + 4224 };
    __shared__ int tok[128];

    const int jt  = blockIdx.x;     // 0..11
    const int mt  = blockIdx.y;     // 0..127
    const int dir = blockIdx.z;
    const float* __restrict__ W   = dir ? g_Wr[1] : g_Wr[0];
    const float* __restrict__ bin = dir ? bb : bf;
    const int j0 = jt * 128;
    const int m0 = mt * 128;

    const int tid  = threadIdx.x;
    const int warp = tid >> 5;
    const int lane = tid & 31;
    const int g    = lane >> 2;
    const int tg   = lane & 3;
    const int wm0  = (warp >> 2) * 64;
    const int wn0  = (warp & 3) * 32;

    if (tid < 128) {
        int m = m0 + tid;
        tok[tid] = x[(m & 63) * T_ + (m >> 6)];
    }
    __syncthreads();

    // per-thread staging coordinates (4 A float4s + 4 B float4s per chunk)
    int ar[4], aq[4], bk[4], bn[4];
#pragma unroll
    for (int it = 0; it < 4; ++it) {
        int i2 = it * 256 + tid;
        ar[it] = i2 >> 3;            // 0..127
        aq[it] = (i2 & 7) * 4;       // 0..28
        bk[it] = i2 >> 5;            // 0..31
        bn[it] = (i2 & 31) * 4;      // 0..124
    }
    uint32_t asu[2] = { smem_u32(Asb[0]), smem_u32(Asb[1]) };
    uint32_t bsu[2] = { smem_u32(Bsb[0]), smem_u32(Bsb[1]) };

    // issue chunk kc into buffer buf
    auto issue = [&](int kc, int buf) {
        const int k0 = kc * 32;
#pragma unroll
        for (int it = 0; it < 4; ++it) {
            CP_ASYNC16(asu[buf] + (uint32_t)(ar[it] * 36 + aq[it]) * 4,
                       &g_embr[(size_t)tok[ar[it]] * D_ + k0 + aq[it]]);
            CP_ASYNC16(bsu[buf] + (uint32_t)(bk[it] * 132 + bn[it]) * 4,
                       &W[(size_t)(k0 + bk[it]) * G3 + j0 + bn[it]]);
        }
    };

    float acc[4][4][4];
#pragma unroll
    for (int mi = 0; mi < 4; ++mi)
#pragma unroll
        for (int ni = 0; ni < 4; ++ni)
#pragma unroll
            for (int q = 0; q < 4; ++q) acc[mi][ni][q] = 0.f;

    issue(0, 0);
    CP_COMMIT();

    for (int kc = 0; kc < 16; ++kc) {
        if (kc < 15) { issue(kc + 1, (kc + 1) & 1); CP_COMMIT(); }
        if (kc < 15) { CP_WAIT(1); } else { CP_WAIT(0); }
        __syncthreads();

        const float* As = Asb[kc & 1];
        const float* Bs = Bsb[kc & 1];
#pragma unroll
        for (int k8 = 0; k8 < 4; ++k8) {
            const int kk = k8 * 8;
            uint32_t bfr[4][2];
#pragma unroll
            for (int ni = 0; ni < 4; ++ni) {
                int n = wn0 + ni * 8 + g;
                bfr[ni][0] = __float_as_uint(Bs[(kk + tg) * 132 + n]);
                bfr[ni][1] = __float_as_uint(Bs[(kk + tg + 4) * 132 + n]);
            }
#pragma unroll
            for (int mi = 0; mi < 4; ++mi) {
                int mr = wm0 + mi * 16 + g;
                uint32_t afr[4];
                afr[0] = __float_as_uint(As[mr * 36 + kk + tg]);
                afr[1] = __float_as_uint(As[(mr + 8) * 36 + kk + tg]);
                afr[2] = __float_as_uint(As[mr * 36 + kk + tg + 4]);
                afr[3] = __float_as_uint(As[(mr + 8) * 36 + kk + tg + 4]);
#pragma unroll
                for (int ni = 0; ni < 4; ++ni) {
                    asm volatile(
                        "mma.sync.aligned.m16n8k8.row.col.f32.tf32.tf32.f32 "
                        "{%0,%1,%2,%3}, {%4,%5,%6,%7}, {%8,%9}, {%0,%1,%2,%3};"
                        : "+f"(acc[mi][ni][0]), "+f"(acc[mi][ni][1]),
                          "+f"(acc[mi][ni][2]), "+f"(acc[mi][ni][3])
                        : "r"(afr[0]), "r"(afr[1]), "r"(afr[2]), "r"(afr[3]),
                          "r"(bfr[ni][0]), "r"(bfr[ni][1]));
                }
            }
        }
        __syncthreads();   // compute done before this buffer is refilled
    }

#pragma unroll
    for (int mi = 0; mi < 4; ++mi) {
        int m_lo = m0 + wm0 + mi * 16 + g;
        int m_hi = m_lo + 8;
#pragma unroll
        for (int ni = 0; ni < 4; ++ni) {
            int c = j0 + wn0 + ni * 8 + 2 * tg;
            float2 bi = *(const float2*)&bin[c];
            float2 v0 = make_float2(acc[mi][ni][0] + bi.x, acc[mi][ni][1] + bi.y);
            float2 v1 = make_float2(acc[mi][ni][2] + bi.x, acc[mi][ni][3] + bi.y);
            *(float2*)&g_GX[dir][m_lo >> 6][m_lo & 63][c] = v0;
            *(float2*)&g_GX[dir][m_hi >> 6][m_hi & 63][c] = v1;
        }
    }
}

// ======================================================================
// Kernel 2: persistent bidirectional GRU recurrence (R12 math, proven).
// Changes: GX + mask prefetched at top of step; hold carried in registers.
// ======================================================================
__global__ __launch_bounds__(256, 1)
void k_recurrence(const int* __restrict__ x,
                  const float* __restrict__ Uf,
                  const float* __restrict__ Ub,
                  const float* __restrict__ bf,
                  const float* __restrict__ bb,
                  float* __restrict__ out)
{
    extern __shared__ __nv_bfloat16 smem_bf[];
    __nv_bfloat16* h_hi = smem_bf;                    // [32][136]
    __nv_bfloat16* h_lo = smem_bf + 32 * 136;         // [32][136]
    __nv_bfloat16* u_hi = smem_bf + 64 * 136;         // [192][136]
    __nv_bfloat16* u_lo = smem_bf + 64 * 136 + 192 * 136;

    const int bid = blockIdx.x;     // 0..127
    const int tid = threadIdx.x;    // 0..255
    const int kc  = bid & 3;
    const int ut  = (bid >> 2) & 7;
    const int bt  = (bid >> 5) & 1;
    const int dir = bid >> 6;
    const int b0 = bt * 32, u0 = ut * 64, k0 = kc * 128;
    const int grp = dir * 2 + bt;   // barrier group (32 blocks)
    const float* __restrict__ Uw = dir ? Ub : Uf;

    // one-time: U slice -> bf16 hi/lo, rows o = gate*64 + unit-local (192 x 128)
    for (int v = tid; v < 192 * 128; v += 256) {
        int o = v >> 7;
        int k = v & 127;
        int gate = o >> 6, ul = o & 63;
        float w = Uw[(size_t)(k0 + k) * G3 + gate * 512 + u0 + ul];
        __nv_bfloat16 wh = __float2bfloat16(w);
        u_hi[o * 136 + k] = wh;
        u_lo[o * 136 + k] = __float2bfloat16(w - __bfloat162float(wh));
    }

    // init H = 0
    if (ut == 0) {
        for (int j = tid; j < 32 * 128; j += 256) {
            int b = j >> 7, k = j & 127;
            g_H[dir][b0 + b][k0 + k] = 0.f;
        }
    }
    grp_sync(grp, 32);

    // phase-A warp tiling: warp -> m-tile (warp&1)*16, n-base (warp>>1)*48
    const int warp  = tid >> 5;
    const int lane  = tid & 31;
    const int g     = lane >> 2;
    const int tg    = lane & 3;
    const int mrow  = (warp & 1) * 16;
    const int nbase = (warp >> 1) * 48;

    // phase-B constants (group mapping: block owns batch bB within its bt tile)
    const int bB = b0 + (bid & 31);
    const int u  = 2 * tid;
    const float* __restrict__ brr = (dir ? bb : bf) + G3;
    const float2 bz  = *(const float2*)&brr[u];
    const float2 brc = *(const float2*)&brr[512 + u];
    const float2 bhc = *(const float2*)&brr[1024 + u];

    float2 hold = make_float2(0.f, 0.f);    // register-carried H[bB][u..u+1]
    float* __restrict__ state = out + (size_t)B_ * T_ * 1024;

    for (int s = 0; s < T_; ++s) {
        const int t = dir ? (T_ - 1 - s) : s;

        // ---- prefetch phase-B inputs (consumed after barrier 1) -----------
        const bool m = (x[bB * T_ + t] != 0);
        const float* __restrict__ gx = &g_GX[dir][t][bB][0];
        float2 xz = __ldcg((const float2*)&gx[u]);
        float2 xr = __ldcg((const float2*)&gx[512 + u]);
        float2 xh = __ldcg((const float2*)&gx[1024 + u]);

        // ---- stage h: global fp32 -> smem bf16 hi/lo ----------------------
        for (int j4 = tid; j4 < 1024; j4 += 256) {
            int b  = j4 >> 5;
            int kv = (j4 & 31) * 4;
            float4 v = __ldcg((const float4*)&g_H[dir][b0 + b][k0 + kv]);
            int base = b * 136 + kv;
            __nv_bfloat16 t0 = __float2bfloat16(v.x);
            __nv_bfloat16 t1 = __float2bfloat16(v.y);
            __nv_bfloat16 t2 = __float2bfloat16(v.z);
            __nv_bfloat16 t3 = __float2bfloat16(v.w);
            h_hi[base + 0] = t0; h_hi[base + 1] = t1;
            h_hi[base + 2] = t2; h_hi[base + 3] = t3;
            h_lo[base + 0] = __float2bfloat16(v.x - __bfloat162float(t0));
            h_lo[base + 1] = __float2bfloat16(v.y - __bfloat162float(t1));
            h_lo[base + 2] = __float2bfloat16(v.z - __bfloat162float(t2));
            h_lo[base + 3] = __float2bfloat16(v.w - __bfloat162float(t3));
        }
        __syncthreads();

        // ---- phase A: gh partial = h @ Uw via split-bf16 mma (3 passes) ---
        float acc[6][4];
#pragma unroll
        for (int ni = 0; ni < 6; ++ni)
#pragma unroll
            for (int q = 0; q < 4; ++q) acc[ni][q] = 0.f;

#pragma unroll
        for (int k8 = 0; k8 < 8; ++k8) {
            const int kk = k8 * 16 + 2 * tg;
            uint32_t ah[4], al[4];
            ah[0] = *(const uint32_t*)&h_hi[(mrow + g) * 136 + kk];
            ah[1] = *(const uint32_t*)&h_hi[(mrow + g + 8) * 136 + kk];
            ah[2] = *(const uint32_t*)&h_hi[(mrow + g) * 136 + kk + 8];
            ah[3] = *(const uint32_t*)&h_hi[(mrow + g + 8) * 136 + kk + 8];
            al[0] = *(const uint32_t*)&h_lo[(mrow + g) * 136 + kk];
            al[1] = *(const uint32_t*)&h_lo[(mrow + g + 8) * 136 + kk];
            al[2] = *(const uint32_t*)&h_lo[(mrow + g) * 136 + kk + 8];
            al[3] = *(const uint32_t*)&h_lo[(mrow + g + 8) * 136 + kk + 8];
#pragma unroll
            for (int ni = 0; ni < 6; ++ni) {
                const int orow = nbase + ni * 8 + g;
                uint32_t bh0 = *(const uint32_t*)&u_hi[orow * 136 + kk];
                uint32_t bh1 = *(const uint32_t*)&u_hi[orow * 136 + kk + 8];
                uint32_t bl0 = *(const uint32_t*)&u_lo[orow * 136 + kk];
                uint32_t bl1 = *(const uint32_t*)&u_lo[orow * 136 + kk + 8];
                mma_bf16(acc[ni], ah, bh0, bh1);
                mma_bf16(acc[ni], al, bh0, bh1);
                mma_bf16(acc[ni], ah, bl0, bl1);
            }
        }

        // store partials: c0,c1 -> row (mrow+g), c2,c3 -> row (mrow+g+8)
#pragma unroll
        for (int ni = 0; ni < 6; ++ni) {
            int o = nbase + ni * 8 + 2 * tg;
            int gate = o >> 6, ul = o & 63;
            int col = gate * 512 + u0 + ul;
            int r0 = b0 + mrow + g;
            __stcg((float2*)&g_GHp[kc][dir][r0][col],     make_float2(acc[ni][0], acc[ni][1]));
            __stcg((float2*)&g_GHp[kc][dir][r0 + 8][col], make_float2(acc[ni][2], acc[ni][3]));
        }
        grp_sync(grp, 32);

        // ---- phase B: gates + state update + output (own bt tile) --------
        {
            float2 gz = bz, gr = brc, gh = bhc;
#pragma unroll
            for (int c = 0; c < GHC; ++c) {
                float2 a  = __ldcg((const float2*)&g_GHp[c][dir][bB][u]);
                float2 b2 = __ldcg((const float2*)&g_GHp[c][dir][bB][512 + u]);
                float2 c2 = __ldcg((const float2*)&g_GHp[c][dir][bB][1024 + u]);
                gz.x += a.x;  gz.y += a.y;
                gr.x += b2.x; gr.y += b2.y;
                gh.x += c2.x; gh.y += c2.y;
            }

            float2 hn;
            {
                float z  = __fdividef(1.f, 1.f + __expf(-(xz.x + gz.x)));
                float rr = __fdividef(1.f, 1.f + __expf(-(xr.x + gr.x)));
                float a  = xh.x + rr * gh.x;
                float hc = 1.f - __fdividef(2.f, 1.f + __expf(2.f * a));
                hn.x = z * hold.x + (1.f - z) * hc;
                hn.x = m ? hn.x : hold.x;
            }
            {
                float z  = __fdividef(1.f, 1.f + __expf(-(xz.y + gz.y)));
                float rr = __fdividef(1.f, 1.f + __expf(-(xr.y + gr.y)));
                float a  = xh.y + rr * gh.y;
                float hc = 1.f - __fdividef(2.f, 1.f + __expf(2.f * a));
                hn.y = z * hold.y + (1.f - z) * hc;
                hn.y = m ? hn.y : hold.y;
            }

            hold = hn;
            __stcg((float2*)&g_H[dir][bB][u], hn);
            *(float2*)&out[((size_t)bB * T_ + t) * 1024 + dir * 512 + u] = hn;
            if (s == T_ - 1)
                *(float2*)&state[(size_t)bB * 1024 + dir * 512 + u] = hn;
        }
        grp_sync(grp, 32);
    }
}

// ======================================================================
// Kernel 3: LayerNorm over last dim (1024) of out, in place
// ======================================================================
__global__ __launch_bounds__(256)
void k_layernorm(float* __restrict__ out,
                 const float* __restrict__ gamma,
                 const float* __restrict__ beta)
{
    const int row = blockIdx.x;
    float* p = out + (size_t)row * 1024;
    const int tid = threadIdx.x;

    float4 v = *(const float4*)&p[tid * 4];
    float s = v.x + v.y + v.z + v.w;
    float q = v.x * v.x + v.y * v.y + v.z * v.z + v.w * v.w;
#pragma unroll
    for (int o = 16; o; o >>= 1) {
        s += __shfl_xor_sync(0xFFFFFFFFu, s, o);
        q += __shfl_xor_sync(0xFFFFFFFFu, q, o);
    }
    __shared__ float ss[8], qq[8];
    __shared__ float mean_s, rstd_s;
    if ((tid & 31) == 0) { ss[tid >> 5] = s; qq[tid >> 5] = q; }
    __syncthreads();
    if (tid == 0) {
        float S = 0.f, Q = 0.f;
#pragma unroll
        for (int i = 0; i < 8; ++i) { S += ss[i]; Q += qq[i]; }
        float mean = S * (1.f / 1024.f);
        float var  = Q * (1.f / 1024.f) - mean * mean;
        mean_s = mean;
        rstd_s = rsqrtf(var + 1e-3f);
    }
    __syncthreads();
    float mean = mean_s, rstd = rstd_s;
    float4 g  = *(const float4*)&gamma[tid * 4];
    float4 be = *(const float4*)&beta[tid * 4];
    v.x = (v.x - mean) * rstd * g.x + be.x;
    v.y = (v.y - mean) * rstd * g.y + be.y;
    v.z = (v.z - mean) * rstd * g.z + be.z;
    v.w = (v.w - mean) * rstd * g.w + be.w;
    *(float4*)&p[tid * 4] = v;
}

// ======================================================================
extern "C" void kernel_launch(void* const* d_in, const int* in_sizes, int n_in,
                              void* d_out, int out_size)
{
    const int*   x     = (const int*)  d_in[0];
    const float* emb   = (const float*)d_in[1];
    const float* Wf    = (const float*)d_in[2];
    const float* Uf    = (const float*)d_in[3];
    const float* bf    = (const float*)d_in[4];
    const float* Wb    = (const float*)d_in[5];
    const float* Ub    = (const float*)d_in[6];
    const float* bb    = (const float*)d_in[7];
    const float* gamma = (const float*)d_in[8];
    const float* beta  = (const float*)d_in[9];
    float* out = (float*)d_out;

    const int smem1 = 2 * (4608 + 4224) * 4;          // 70656 B (double-buffered tiles)
    const int smem2 = (64 + 384) * 136 * 2;           // 121856 B
    cudaFuncSetAttribute(k_input_gemm_mma, cudaFuncAttributeMaxDynamicSharedMemorySize, smem1);
    cudaFuncSetAttribute(k_recurrence, cudaFuncAttributeMaxDynamicSharedMemorySize, smem2);

    k_round<<<1024, 256>>>(emb, Wf, Wb);
    dim3 g1(G3 / 128, (T_ * B_) / 128, 2);
    k_input_gemm_mma<<<g1, 256, smem1>>>(x, bf, bb);
    k_recurrence<<<128, 256, smem2>>>(x, Uf, Ub, bf, bb, out);
    k_layernorm<<<B_ * T_, 256>>>(out, gamma, beta);
}

// round 15
// speedup vs baseline: 1.3323x; 1.2740x over previous
#include <cuda_runtime.h>
#include <cuda_bf16.h>
#include <math.h>
#include <stdint.h>

#define B_   64
#define T_   256
#define D_   512
#define U_   512
#define G3   1536   // 3*U
#define V_   32000
#define SU   520    // smem k-stride (bf16 elems): 520/2 % 32 == 4 -> conflict-free frags

typedef unsigned long long ull;

// ---------------- device scratch (static: no runtime allocation) ----------
__device__ float    g_GX[2][T_][B_][G3];       // e@W + b_in, per direction
__device__ uint32_t g_Hp[2][2][B_][U_];        // packed bf16 (hi|lo<<16) H, double-buffered by step parity
__device__ float    g_embr[(size_t)V_ * D_];   // tf32-rounded embedding
__device__ float    g_Wr[2][D_ * G3];          // tf32-rounded W (fwd/bwd)

// per-(dir,bt) barrier state, padded to separate cache lines
struct __align__(128) BarState { unsigned int count; unsigned int gen; unsigned int pad[30]; };
__device__ BarState g_bar[4];

// ---------------- helpers --------------------------------------------------
__device__ __forceinline__ float to_tf32(float v) {
    uint32_t u;
    asm("cvt.rna.tf32.f32 %0, %1;" : "=r"(u) : "f"(v));
    return __uint_as_float(u);
}
__device__ __forceinline__ void mma_bf16(float* c, const uint32_t* a, uint32_t b0, uint32_t b1) {
    asm volatile(
        "mma.sync.aligned.m16n8k16.row.col.f32.bf16.bf16.f32 "
        "{%0,%1,%2,%3}, {%4,%5,%6,%7}, {%8,%9}, {%0,%1,%2,%3};"
        : "+f"(c[0]), "+f"(c[1]), "+f"(c[2]), "+f"(c[3])
        : "r"(a[0]), "r"(a[1]), "r"(a[2]), "r"(a[3]), "r"(b0), "r"(b1));
}
__device__ __forceinline__ uint32_t smem_u32(const void* p) {
    uint32_t a;
    asm("{ .reg .u64 t; cvta.to.shared.u64 t, %1; cvt.u32.u64 %0, t; }" : "=r"(a) : "l"(p));
    return a;
}
__device__ __forceinline__ uint32_t pack_hilo(float v) {
    __nv_bfloat16 hi = __float2bfloat16(v);
    __nv_bfloat16 lo = __float2bfloat16(v - __bfloat162float(hi));
    return (uint32_t)__bfloat16_as_ushort(hi) | ((uint32_t)__bfloat16_as_ushort(lo) << 16);
}
#define CP_ASYNC16(dst_u32, src) \
    asm volatile("cp.async.cg.shared.global [%0], [%1], 16;" :: "r"(dst_u32), "l"(src))
#define CP_COMMIT() asm volatile("cp.async.commit_group;" ::: "memory")
#define CP_WAIT(n)  asm volatile("cp.async.wait_group %0;" :: "n"(n) : "memory")

// ---------------- software barrier over one (dir,bt) group's 32 blocks ----
__device__ __forceinline__ void grp_sync(int grp, unsigned nb) {
    volatile unsigned* vgen = (volatile unsigned*)&g_bar[grp].gen;
    __syncthreads();
    if (threadIdx.x == 0) {
        unsigned gen = *vgen;
        __threadfence();                       // order gen-read & prior stores before arrive
        if (atomicAdd(&g_bar[grp].count, 1u) == nb - 1u) {
            g_bar[grp].count = 0u;
            __threadfence();
            atomicAdd(&g_bar[grp].gen, 1u);
        } else {
            while (*vgen == gen) { }
        }
        __threadfence();                       // acquire
    }
    __syncthreads();
}

// ======================================================================
// Kernel 0: round emb / Wf / Wb to tf32 (rna) into static buffers.
// ======================================================================
__global__ __launch_bounds__(256)
void k_round(const float* __restrict__ emb,
             const float* __restrict__ Wf,
             const float* __restrict__ Wb)
{
    const size_t stride = (size_t)gridDim.x * blockDim.x;
    const size_t i0 = (size_t)blockIdx.x * blockDim.x + threadIdx.x;
    const size_t n_emb4 = (size_t)V_ * D_ / 4;
    const size_t n_w4   = (size_t)D_ * G3 / 4;

    for (size_t i = i0; i < n_emb4; i += stride) {
        float4 v = ((const float4*)emb)[i];
        v.x = to_tf32(v.x); v.y = to_tf32(v.y); v.z = to_tf32(v.z); v.w = to_tf32(v.w);
        ((float4*)g_embr)[i] = v;
    }
    for (size_t i = i0; i < n_w4; i += stride) {
        float4 a = ((const float4*)Wf)[i];
        a.x = to_tf32(a.x); a.y = to_tf32(a.y); a.z = to_tf32(a.z); a.w = to_tf32(a.w);
        ((float4*)g_Wr[0])[i] = a;
        float4 b = ((const float4*)Wb)[i];
        b.x = to_tf32(b.x); b.y = to_tf32(b.y); b.z = to_tf32(b.z); b.w = to_tf32(b.w);
        ((float4*)g_Wr[1])[i] = b;
    }
}

// ======================================================================
// Kernel 1 (mma.sync tf32, cp.async double-buffered) — R14, proven.
// ======================================================================
__global__ __launch_bounds__(256, 2)
void k_input_gemm_mma(const int* __restrict__ x,
                      const float* __restrict__ bf,
                      const float* __restrict__ bb)
{
    extern __shared__ float smem_k1[];
    float* Asb[2] = { smem_k1, smem_k1 + 4608 };
    float* Bsb[2] = { smem_k1 + 9216, smem_k1 + 9216 + 4224 };
    __shared__ int tok[128];

    const int jt  = blockIdx.x;     // 0..11
    const int mt  = blockIdx.y;     // 0..127
    const int dir = blockIdx.z;
    const float* __restrict__ W   = dir ? g_Wr[1] : g_Wr[0];
    const float* __restrict__ bin = dir ? bb : bf;
    const int j0 = jt * 128;
    const int m0 = mt * 128;

    const int tid  = threadIdx.x;
    const int warp = tid >> 5;
    const int lane = tid & 31;
    const int g    = lane >> 2;
    const int tg   = lane & 3;
    const int wm0  = (warp >> 2) * 64;
    const int wn0  = (warp & 3) * 32;

    if (tid < 128) {
        int m = m0 + tid;
        tok[tid] = x[(m & 63) * T_ + (m >> 6)];
    }
    __syncthreads();

    int ar[4], aq[4], bk[4], bn[4];
#pragma unroll
    for (int it = 0; it < 4; ++it) {
        int i2 = it * 256 + tid;
        ar[it] = i2 >> 3;
        aq[it] = (i2 & 7) * 4;
        bk[it] = i2 >> 5;
        bn[it] = (i2 & 31) * 4;
    }
    uint32_t asu[2] = { smem_u32(Asb[0]), smem_u32(Asb[1]) };
    uint32_t bsu[2] = { smem_u32(Bsb[0]), smem_u32(Bsb[1]) };

    auto issue = [&](int kc, int buf) {
        const int k0 = kc * 32;
#pragma unroll
        for (int it = 0; it < 4; ++it) {
            CP_ASYNC16(asu[buf] + (uint32_t)(ar[it] * 36 + aq[it]) * 4,
                       &g_embr[(size_t)tok[ar[it]] * D_ + k0 + aq[it]]);
            CP_ASYNC16(bsu[buf] + (uint32_t)(bk[it] * 132 + bn[it]) * 4,
                       &W[(size_t)(k0 + bk[it]) * G3 + j0 + bn[it]]);
        }
    };

    float acc[4][4][4];
#pragma unroll
    for (int mi = 0; mi < 4; ++mi)
#pragma unroll
        for (int ni = 0; ni < 4; ++ni)
#pragma unroll
            for (int q = 0; q < 4; ++q) acc[mi][ni][q] = 0.f;

    issue(0, 0);
    CP_COMMIT();

    for (int kc = 0; kc < 16; ++kc) {
        if (kc < 15) { issue(kc + 1, (kc + 1) & 1); CP_COMMIT(); }
        if (kc < 15) { CP_WAIT(1); } else { CP_WAIT(0); }
        __syncthreads();

        const float* As = Asb[kc & 1];
        const float* Bs = Bsb[kc & 1];
#pragma unroll
        for (int k8 = 0; k8 < 4; ++k8) {
            const int kk = k8 * 8;
            uint32_t bfr[4][2];
#pragma unroll
            for (int ni = 0; ni < 4; ++ni) {
                int n = wn0 + ni * 8 + g;
                bfr[ni][0] = __float_as_uint(Bs[(kk + tg) * 132 + n]);
                bfr[ni][1] = __float_as_uint(Bs[(kk + tg + 4) * 132 + n]);
            }
#pragma unroll
            for (int mi = 0; mi < 4; ++mi) {
                int mr = wm0 + mi * 16 + g;
                uint32_t afr[4];
                afr[0] = __float_as_uint(As[mr * 36 + kk + tg]);
                afr[1] = __float_as_uint(As[(mr + 8) * 36 + kk + tg]);
                afr[2] = __float_as_uint(As[mr * 36 + kk + tg + 4]);
                afr[3] = __float_as_uint(As[(mr + 8) * 36 + kk + tg + 4]);
#pragma unroll
                for (int ni = 0; ni < 4; ++ni) {
                    asm volatile(
                        "mma.sync.aligned.m16n8k8.row.col.f32.tf32.tf32.f32 "
                        "{%0,%1,%2,%3}, {%4,%5,%6,%7}, {%8,%9}, {%0,%1,%2,%3};"
                        : "+f"(acc[mi][ni][0]), "+f"(acc[mi][ni][1]),
                          "+f"(acc[mi][ni][2]), "+f"(acc[mi][ni][3])
                        : "r"(afr[0]), "r"(afr[1]), "r"(afr[2]), "r"(afr[3]),
                          "r"(bfr[ni][0]), "r"(bfr[ni][1]));
                }
            }
        }
        __syncthreads();
    }

#pragma unroll
    for (int mi = 0; mi < 4; ++mi) {
        int m_lo = m0 + wm0 + mi * 16 + g;
        int m_hi = m_lo + 8;
#pragma unroll
        for (int ni = 0; ni < 4; ++ni) {
            int c = j0 + wn0 + ni * 8 + 2 * tg;
            float2 bi = *(const float2*)&bin[c];
            float2 v0 = make_float2(acc[mi][ni][0] + bi.x, acc[mi][ni][1] + bi.y);
            float2 v1 = make_float2(acc[mi][ni][2] + bi.x, acc[mi][ni][3] + bi.y);
            *(float2*)&g_GX[dir][m_lo >> 6][m_lo & 63][c] = v0;
            *(float2*)&g_GX[dir][m_hi >> 6][m_hi & 63][c] = v1;
        }
    }
}

// ======================================================================
// Kernel 2: persistent bidirectional GRU recurrence — ONE barrier per step.
// 128 blocks = dir(2) x bt(2 of 32 batches) x slice(32 of 16 units).
// Block holds FULL-K U slice (48 outputs x 512 K, bf16 hi/lo) in smem ->
// phase A produces complete gh for its region (K split over warp pairs,
// reduced in smem); phase B is block-local. H crosses blocks as packed
// bf16 (hi|lo) words, double-buffered by step parity.
// ======================================================================
__global__ __launch_bounds__(256, 1)
void k_recurrence(const int* __restrict__ x,
                  const float* __restrict__ Uf,
                  const float* __restrict__ Ub,
                  const float* __restrict__ bf,
                  const float* __restrict__ bb,
                  float* __restrict__ out)
{
    extern __shared__ char smem_raw[];
    __nv_bfloat16* u_hi = (__nv_bfloat16*)smem_raw;                 // [48][SU]
    __nv_bfloat16* u_lo = (__nv_bfloat16*)(smem_raw + 49920);       // [48][SU]
    __nv_bfloat16* h_hi = (__nv_bfloat16*)(smem_raw + 99840);       // [32][SU]
    __nv_bfloat16* h_lo = (__nv_bfloat16*)(smem_raw + 133120);      // [32][SU]
    float*         red  = (float*)(smem_raw + 166400);              // [4q][3ni][32 lanes][4]
    float*         ghs  = (float*)(smem_raw + 172544);              // [48][33]

    const int bid   = blockIdx.x;     // 0..127
    const int tid   = threadIdx.x;    // 0..255
    const int slice = bid & 31;
    const int bt    = (bid >> 5) & 1;
    const int dir   = bid >> 6;
    const int b0 = bt * 32, u0 = slice * 16;
    const int grp = dir * 2 + bt;
    const float* __restrict__ Uw = dir ? Ub : Uf;

    // one-time: full-K U slice -> bf16 hi/lo. rows o = gate*16 + unit-local
    for (int v = tid; v < 48 * 512; v += 256) {
        int o = v >> 9;
        int k = v & 511;
        float w = Uw[(size_t)k * G3 + (o >> 4) * 512 + u0 + (o & 15)];
        __nv_bfloat16 wh = __float2bfloat16(w);
        u_hi[o * SU + k] = wh;
        u_lo[o * SU + k] = __float2bfloat16(w - __bfloat162float(wh));
    }

    // phase-B ownership: thread -> (batch pb, unit pair pu)
    const int pb = tid >> 3;             // 0..31
    const int pu = 2 * (tid & 7);        // 0..14
    const int bB = b0 + pb;
    const int u  = u0 + pu;              // global unit (even)

    // init H = 0 in parity-0 buffer (own region)
    *(uint2*)&g_Hp[0][dir][bB][u] = make_uint2(0u, 0u);
    grp_sync(grp, 32);

    // phase-A warp tiling: q = warp&3 -> (m-half, n-trio); kh = warp>>2 -> K half
    const int warp = tid >> 5;
    const int lane = tid & 31;
    const int g    = lane >> 2;
    const int tg   = lane & 3;
    const int q    = warp & 3;
    const int kh   = warp >> 2;
    const int m0w  = (q & 1) * 16;
    const int n0w  = (q >> 1) * 24;
    const int kbase = kh * 256;

    const float* __restrict__ brr = (dir ? bb : bf) + G3;
    const float2 bz  = *(const float2*)&brr[u];
    const float2 brc = *(const float2*)&brr[512 + u];
    const float2 bhc = *(const float2*)&brr[1024 + u];

    float2 hold = make_float2(0.f, 0.f);
    float* __restrict__ state = out + (size_t)B_ * T_ * 1024;

    for (int s = 0; s < T_; ++s) {
        const int t  = dir ? (T_ - 1 - s) : s;
        const int rp = s & 1;
        const int wp = rp ^ 1;

        // ---- prefetch phase-B inputs ---------------------------------------
        const bool m = (x[bB * T_ + t] != 0);
        const float* __restrict__ gx = &g_GX[dir][t][bB][0];
        float2 xz = __ldcg((const float2*)&gx[u]);
        float2 xr = __ldcg((const float2*)&gx[512 + u]);
        float2 xh = __ldcg((const float2*)&gx[1024 + u]);

        // ---- stage h: packed gmem -> smem hi/lo (byte_perm unpack) ---------
        for (int j4 = tid; j4 < 4096; j4 += 256) {
            int b  = j4 >> 7;                 // 0..31
            int kv = (j4 & 127) * 4;          // 0..508
            uint4 w = __ldcg((const uint4*)&g_Hp[rp][dir][b0 + b][kv]);
            uint32_t hi01 = __byte_perm(w.x, w.y, 0x5410);
            uint32_t hi23 = __byte_perm(w.z, w.w, 0x5410);
            uint32_t lo01 = __byte_perm(w.x, w.y, 0x7632);
            uint32_t lo23 = __byte_perm(w.z, w.w, 0x7632);
            *(uint2*)&h_hi[b * SU + kv] = make_uint2(hi01, hi23);
            *(uint2*)&h_lo[b * SU + kv] = make_uint2(lo01, lo23);
        }
        __syncthreads();

        // ---- phase A: gh = h @ Uw (split-bf16, 3 passes, K-half per warp) --
        float acc[3][4];
#pragma unroll
        for (int ni = 0; ni < 3; ++ni)
#pragma unroll
            for (int j = 0; j < 4; ++j) acc[ni][j] = 0.f;

#pragma unroll 4
        for (int k8 = 0; k8 < 16; ++k8) {
            const int kk = kbase + k8 * 16 + 2 * tg;
            uint32_t ah[4], al[4];
            ah[0] = *(const uint32_t*)&h_hi[(m0w + g) * SU + kk];
            ah[1] = *(const uint32_t*)&h_hi[(m0w + g + 8) * SU + kk];
            ah[2] = *(const uint32_t*)&h_hi[(m0w + g) * SU + kk + 8];
            ah[3] = *(const uint32_t*)&h_hi[(m0w + g + 8) * SU + kk + 8];
            al[0] = *(const uint32_t*)&h_lo[(m0w + g) * SU + kk];
            al[1] = *(const uint32_t*)&h_lo[(m0w + g + 8) * SU + kk];
            al[2] = *(const uint32_t*)&h_lo[(m0w + g) * SU + kk + 8];
            al[3] = *(const uint32_t*)&h_lo[(m0w + g + 8) * SU + kk + 8];
#pragma unroll
            for (int ni = 0; ni < 3; ++ni) {
                const int orow = n0w + ni * 8 + g;
                uint32_t bh0 = *(const uint32_t*)&u_hi[orow * SU + kk];
                uint32_t bh1 = *(const uint32_t*)&u_hi[orow * SU + kk + 8];
                uint32_t bl0 = *(const uint32_t*)&u_lo[orow * SU + kk];
                uint32_t bl1 = *(const uint32_t*)&u_lo[orow * SU + kk + 8];
                mma_bf16(acc[ni], ah, bh0, bh1);
                mma_bf16(acc[ni], al, bh0, bh1);
                mma_bf16(acc[ni], ah, bl0, bl1);
            }
        }

        // ---- cross-K-half reduction + ghs publish --------------------------
        if (kh == 1) {
#pragma unroll
            for (int ni = 0; ni < 3; ++ni)
                *(float4*)&red[((q * 3 + ni) * 32 + lane) * 4] = *(float4*)acc[ni];
        }
        __syncthreads();
        if (kh == 0) {
#pragma unroll
            for (int ni = 0; ni < 3; ++ni) {
                float4 r = *(const float4*)&red[((q * 3 + ni) * 32 + lane) * 4];
                acc[ni][0] += r.x; acc[ni][1] += r.y;
                acc[ni][2] += r.z; acc[ni][3] += r.w;
                int o = n0w + ni * 8 + 2 * tg;
                ghs[o * 33 + m0w + g]           = acc[ni][0];
                ghs[(o + 1) * 33 + m0w + g]     = acc[ni][1];
                ghs[o * 33 + m0w + g + 8]       = acc[ni][2];
                ghs[(o + 1) * 33 + m0w + g + 8] = acc[ni][3];
            }
        }
        __syncthreads();

        // ---- phase B: block-local gates + H update --------------------------
        {
            float2 gz = make_float2(bz.x  + ghs[pu * 33 + pb],        bz.y  + ghs[(pu + 1) * 33 + pb]);
            float2 gr = make_float2(brc.x + ghs[(16 + pu) * 33 + pb], brc.y + ghs[(17 + pu) * 33 + pb]);
            float2 gh = make_float2(bhc.x + ghs[(32 + pu) * 33 + pb], bhc.y + ghs[(33 + pu) * 33 + pb]);

            float2 hn;
            {
                float z  = __fdividef(1.f, 1.f + __expf(-(xz.x + gz.x)));
                float rr = __fdividef(1.f, 1.f + __expf(-(xr.x + gr.x)));
                float a  = xh.x + rr * gh.x;
                float hc = 1.f - __fdividef(2.f, 1.f + __expf(2.f * a));
                hn.x = z * hold.x + (1.f - z) * hc;
                hn.x = m ? hn.x : hold.x;
            }
            {
                float z  = __fdividef(1.f, 1.f + __expf(-(xz.y + gz.y)));
                float rr = __fdividef(1.f, 1.f + __expf(-(xr.y + gr.y)));
                float a  = xh.y + rr * gh.y;
                float hc = 1.f - __fdividef(2.f, 1.f + __expf(2.f * a));
                hn.y = z * hold.y + (1.f - z) * hc;
                hn.y = m ? hn.y : hold.y;
            }

            hold = hn;
            *(uint2*)&g_Hp[wp][dir][bB][u] = make_uint2(pack_hilo(hn.x), pack_hilo(hn.y));
            *(float2*)&out[((size_t)bB * T_ + t) * 1024 + dir * 512 + u] = hn;
            if (s == T_ - 1)
                *(float2*)&state[(size_t)bB * 1024 + dir * 512 + u] = hn;
        }
        grp_sync(grp, 32);   // H writes visible before next step's stage
    }
}

// ======================================================================
// Kernel 3: LayerNorm over last dim (1024) of out, in place
// ======================================================================
__global__ __launch_bounds__(256)
void k_layernorm(float* __restrict__ out,
                 const float* __restrict__ gamma,
                 const float* __restrict__ beta)
{
    const int row = blockIdx.x;
    float* p = out + (size_t)row * 1024;
    const int tid = threadIdx.x;

    float4 v = *(const float4*)&p[tid * 4];
    float s = v.x + v.y + v.z + v.w;
    float q = v.x * v.x + v.y * v.y + v.z * v.z + v.w * v.w;
#pragma unroll
    for (int o = 16; o; o >>= 1) {
        s += __shfl_xor_sync(0xFFFFFFFFu, s, o);
        q += __shfl_xor_sync(0xFFFFFFFFu, q, o);
    }
    __shared__ float ss[8], qq[8];
    __shared__ float mean_s, rstd_s;
    if ((tid & 31) == 0) { ss[tid >> 5] = s; qq[tid >> 5] = q; }
    __syncthreads();
    if (tid == 0) {
        float S = 0.f, Q = 0.f;
#pragma unroll
        for (int i = 0; i < 8; ++i) { S += ss[i]; Q += qq[i]; }
        float mean = S * (1.f / 1024.f);
        float var  = Q * (1.f / 1024.f) - mean * mean;
        mean_s = mean;
        rstd_s = rsqrtf(var + 1e-3f);
    }
    __syncthreads();
    float mean = mean_s, rstd = rstd_s;
    float4 g  = *(const float4*)&gamma[tid * 4];
    float4 be = *(const float4*)&beta[tid * 4];
    v.x = (v.x - mean) * rstd * g.x + be.x;
    v.y = (v.y - mean) * rstd * g.y + be.y;
    v.z = (v.z - mean) * rstd * g.z + be.z;
    v.w = (v.w - mean) * rstd * g.w + be.w;
    *(float4*)&p[tid * 4] = v;
}

// ======================================================================
extern "C" void kernel_launch(void* const* d_in, const int* in_sizes, int n_in,
                              void* d_out, int out_size)
{
    const int*   x     = (const int*)  d_in[0];
    const float* emb   = (const float*)d_in[1];
    const float* Wf    = (const float*)d_in[2];
    const float* Uf    = (const float*)d_in[3];
    const float* bf    = (const float*)d_in[4];
    const float* Wb    = (const float*)d_in[5];
    const float* Ub    = (const float*)d_in[6];
    const float* bb    = (const float*)d_in[7];
    const float* gamma = (const float*)d_in[8];
    const float* beta  = (const float*)d_in[9];
    float* out = (float*)d_out;

    const int smem1 = 2 * (4608 + 4224) * 4;                 // 70656 B
    const int smem2 = 166400 + 6144 + 48 * 33 * 4;           // 178880 B
    cudaFuncSetAttribute(k_input_gemm_mma, cudaFuncAttributeMaxDynamicSharedMemorySize, smem1);
    cudaFuncSetAttribute(k_recurrence, cudaFuncAttributeMaxDynamicSharedMemorySize, smem2);

    k_round<<<1024, 256>>>(emb, Wf, Wb);
    dim3 g1(G3 / 128, (T_ * B_) / 128, 2);
    k_input_gemm_mma<<<g1, 256, smem1>>>(x, bf, bb);
    k_recurrence<<<128, 256, smem2>>>(x, Uf, Ub, bf, bb, out);
    k_layernorm<<<B_ * T_, 256>>>(out, gamma, beta);
}

// round 16
// speedup vs baseline: 1.4272x; 1.0712x over previous
#include <cuda_runtime.h>
#include <cuda_bf16.h>
#include <math.h>
#include <stdint.h>

#define B_   64
#define T_   256
#define D_   512
#define U_   512
#define G3   1536   // 3*U
#define V_   32000
#define SU   520    // smem k-stride (bf16 elems): row pitch 1040B -> conflict-free, 16B-aligned

// ---------------- device scratch (static: no runtime allocation) ----------
__device__ float         g_GX[2][T_][B_][G3];     // e@W + b_in, per direction
__device__ __nv_bfloat16 g_Hhi[2][2][B_][U_];     // H hi, double-buffered by parity
__device__ __nv_bfloat16 g_Hlo[2][2][B_][U_];     // H lo
__device__ float         g_embr[(size_t)V_ * D_]; // tf32-rounded embedding
__device__ float         g_Wr[2][D_ * G3];        // tf32-rounded W (fwd/bwd)

// per-(dir,bt) barrier state, padded to separate cache lines
struct __align__(128) BarState { unsigned int count; unsigned int gen; unsigned int pad[30]; };
__device__ BarState g_bar[4];

// ---------------- helpers --------------------------------------------------
__device__ __forceinline__ float to_tf32(float v) {
    uint32_t u;
    asm("cvt.rna.tf32.f32 %0, %1;" : "=r"(u) : "f"(v));
    return __uint_as_float(u);
}
__device__ __forceinline__ void mma_bf16(float* c, const uint32_t* a, uint32_t b0, uint32_t b1) {
    asm volatile(
        "mma.sync.aligned.m16n8k16.row.col.f32.bf16.bf16.f32 "
        "{%0,%1,%2,%3}, {%4,%5,%6,%7}, {%8,%9}, {%0,%1,%2,%3};"
        : "+f"(c[0]), "+f"(c[1]), "+f"(c[2]), "+f"(c[3])
        : "r"(a[0]), "r"(a[1]), "r"(a[2]), "r"(a[3]), "r"(b0), "r"(b1));
}
__device__ __forceinline__ uint32_t smem_u32(const void* p) {
    uint32_t a;
    asm("{ .reg .u64 t; cvta.to.shared.u64 t, %1; cvt.u32.u64 %0, t; }" : "=r"(a) : "l"(p));
    return a;
}
#define LDMX4(r0, r1, r2, r3, addr) \
    asm volatile("ldmatrix.sync.aligned.m8n8.x4.shared.b16 {%0,%1,%2,%3}, [%4];" \
                 : "=r"(r0), "=r"(r1), "=r"(r2), "=r"(r3) : "r"(addr))
#define LDMX2(r0, r1, addr) \
    asm volatile("ldmatrix.sync.aligned.m8n8.x2.shared.b16 {%0,%1}, [%2];" \
                 : "=r"(r0), "=r"(r1) : "r"(addr))
#define CP_ASYNC16(dst_u32, src) \
    asm volatile("cp.async.cg.shared.global [%0], [%1], 16;" :: "r"(dst_u32), "l"(src))
#define CP_COMMIT() asm volatile("cp.async.commit_group;" ::: "memory")
#define CP_WAIT(n)  asm volatile("cp.async.wait_group %0;" :: "n"(n) : "memory")

// ---------------- software barrier over one (dir,bt) group's 32 blocks ----
__device__ __forceinline__ void grp_sync(int grp, unsigned nb) {
    volatile unsigned* vgen = (volatile unsigned*)&g_bar[grp].gen;
    __syncthreads();
    if (threadIdx.x == 0) {
        unsigned gen = *vgen;
        __threadfence();                       // order gen-read & prior stores before arrive
        if (atomicAdd(&g_bar[grp].count, 1u) == nb - 1u) {
            g_bar[grp].count = 0u;
            __threadfence();
            atomicAdd(&g_bar[grp].gen, 1u);
        } else {
            while (*vgen == gen) { }
        }
        __threadfence();                       // acquire
    }
    __syncthreads();
}

// ======================================================================
// Kernel 0: round emb / Wf / Wb to tf32 (rna) into static buffers.
// ======================================================================
__global__ __launch_bounds__(256)
void k_round(const float* __restrict__ emb,
             const float* __restrict__ Wf,
             const float* __restrict__ Wb)
{
    const size_t stride = (size_t)gridDim.x * blockDim.x;
    const size_t i0 = (size_t)blockIdx.x * blockDim.x + threadIdx.x;
    const size_t n_emb4 = (size_t)V_ * D_ / 4;
    const size_t n_w4   = (size_t)D_ * G3 / 4;

    for (size_t i = i0; i < n_emb4; i += stride) {
        float4 v = ((const float4*)emb)[i];
        v.x = to_tf32(v.x); v.y = to_tf32(v.y); v.z = to_tf32(v.z); v.w = to_tf32(v.w);
        ((float4*)g_embr)[i] = v;
    }
    for (size_t i = i0; i < n_w4; i += stride) {
        float4 a = ((const float4*)Wf)[i];
        a.x = to_tf32(a.x); a.y = to_tf32(a.y); a.z = to_tf32(a.z); a.w = to_tf32(a.w);
        ((float4*)g_Wr[0])[i] = a;
        float4 b = ((const float4*)Wb)[i];
        b.x = to_tf32(b.x); b.y = to_tf32(b.y); b.z = to_tf32(b.z); b.w = to_tf32(b.w);
        ((float4*)g_Wr[1])[i] = b;
    }
}

// ======================================================================
// Kernel 1 (mma.sync tf32, cp.async double-buffered) — R14, proven.
// ======================================================================
__global__ __launch_bounds__(256, 2)
void k_input_gemm_mma(const int* __restrict__ x,
                      const float* __restrict__ bf,
                      const float* __restrict__ bb)
{
    extern __shared__ float smem_k1[];
    float* Asb[2] = { smem_k1, smem_k1 + 4608 };
    float* Bsb[2] = { smem_k1 + 9216, smem_k1 + 9216 + 4224 };
    __shared__ int tok[128];

    const int jt  = blockIdx.x;     // 0..11
    const int mt  = blockIdx.y;     // 0..127
    const int dir = blockIdx.z;
    const float* __restrict__ W   = dir ? g_Wr[1] : g_Wr[0];
    const float* __restrict__ bin = dir ? bb : bf;
    const int j0 = jt * 128;
    const int m0 = mt * 128;

    const int tid  = threadIdx.x;
    const int warp = tid >> 5;
    const int lane = tid & 31;
    const int g    = lane >> 2;
    const int tg   = lane & 3;
    const int wm0  = (warp >> 2) * 64;
    const int wn0  = (warp & 3) * 32;

    if (tid < 128) {
        int m = m0 + tid;
        tok[tid] = x[(m & 63) * T_ + (m >> 6)];
    }
    __syncthreads();

    int ar[4], aq[4], bk[4], bn[4];
#pragma unroll
    for (int it = 0; it < 4; ++it) {
        int i2 = it * 256 + tid;
        ar[it] = i2 >> 3;
        aq[it] = (i2 & 7) * 4;
        bk[it] = i2 >> 5;
        bn[it] = (i2 & 31) * 4;
    }
    uint32_t asu[2] = { smem_u32(Asb[0]), smem_u32(Asb[1]) };
    uint32_t bsu[2] = { smem_u32(Bsb[0]), smem_u32(Bsb[1]) };

    auto issue = [&](int kc, int buf) {
        const int k0 = kc * 32;
#pragma unroll
        for (int it = 0; it < 4; ++it) {
            CP_ASYNC16(asu[buf] + (uint32_t)(ar[it] * 36 + aq[it]) * 4,
                       &g_embr[(size_t)tok[ar[it]] * D_ + k0 + aq[it]]);
            CP_ASYNC16(bsu[buf] + (uint32_t)(bk[it] * 132 + bn[it]) * 4,
                       &W[(size_t)(k0 + bk[it]) * G3 + j0 + bn[it]]);
        }
    };

    float acc[4][4][4];
#pragma unroll
    for (int mi = 0; mi < 4; ++mi)
#pragma unroll
        for (int ni = 0; ni < 4; ++ni)
#pragma unroll
            for (int q = 0; q < 4; ++q) acc[mi][ni][q] = 0.f;

    issue(0, 0);
    CP_COMMIT();

    for (int kc = 0; kc < 16; ++kc) {
        if (kc < 15) { issue(kc + 1, (kc + 1) & 1); CP_COMMIT(); }
        if (kc < 15) { CP_WAIT(1); } else { CP_WAIT(0); }
        __syncthreads();

        const float* As = Asb[kc & 1];
        const float* Bs = Bsb[kc & 1];
#pragma unroll
        for (int k8 = 0; k8 < 4; ++k8) {
            const int kk = k8 * 8;
            uint32_t bfr[4][2];
#pragma unroll
            for (int ni = 0; ni < 4; ++ni) {
                int n = wn0 + ni * 8 + g;
                bfr[ni][0] = __float_as_uint(Bs[(kk + tg) * 132 + n]);
                bfr[ni][1] = __float_as_uint(Bs[(kk + tg + 4) * 132 + n]);
            }
#pragma unroll
            for (int mi = 0; mi < 4; ++mi) {
                int mr = wm0 + mi * 16 + g;
                uint32_t afr[4];
                afr[0] = __float_as_uint(As[mr * 36 + kk + tg]);
                afr[1] = __float_as_uint(As[(mr + 8) * 36 + kk + tg]);
                afr[2] = __float_as_uint(As[mr * 36 + kk + tg + 4]);
                afr[3] = __float_as_uint(As[(mr + 8) * 36 + kk + tg + 4]);
#pragma unroll
                for (int ni = 0; ni < 4; ++ni) {
                    asm volatile(
                        "mma.sync.aligned.m16n8k8.row.col.f32.tf32.tf32.f32 "
                        "{%0,%1,%2,%3}, {%4,%5,%6,%7}, {%8,%9}, {%0,%1,%2,%3};"
                        : "+f"(acc[mi][ni][0]), "+f"(acc[mi][ni][1]),
                          "+f"(acc[mi][ni][2]), "+f"(acc[mi][ni][3])
                        : "r"(afr[0]), "r"(afr[1]), "r"(afr[2]), "r"(afr[3]),
                          "r"(bfr[ni][0]), "r"(bfr[ni][1]));
                }
            }
        }
        __syncthreads();
    }

#pragma unroll
    for (int mi = 0; mi < 4; ++mi) {
        int m_lo = m0 + wm0 + mi * 16 + g;
        int m_hi = m_lo + 8;
#pragma unroll
        for (int ni = 0; ni < 4; ++ni) {
            int c = j0 + wn0 + ni * 8 + 2 * tg;
            float2 bi = *(const float2*)&bin[c];
            float2 v0 = make_float2(acc[mi][ni][0] + bi.x, acc[mi][ni][1] + bi.y);
            float2 v1 = make_float2(acc[mi][ni][2] + bi.x, acc[mi][ni][3] + bi.y);
            *(float2*)&g_GX[dir][m_lo >> 6][m_lo & 63][c] = v0;
            *(float2*)&g_GX[dir][m_hi >> 6][m_hi & 63][c] = v1;
        }
    }
}

// ======================================================================
// Kernel 2: persistent bidirectional GRU recurrence — ONE barrier per step
// (R15 structure, proven). Changes this round:
//  - fragment loads via ldmatrix (6 ops/k8 vs 20 LDS.32)
//  - H staged via cp.async from separate hi/lo bf16 gmem buffers (no unpack)
// ======================================================================
__global__ __launch_bounds__(256, 1)
void k_recurrence(const int* __restrict__ x,
                  const float* __restrict__ Uf,
                  const float* __restrict__ Ub,
                  const float* __restrict__ bf,
                  const float* __restrict__ bb,
                  float* __restrict__ out)
{
    extern __shared__ char smem_raw[];
    __nv_bfloat16* u_hi = (__nv_bfloat16*)smem_raw;                 // [48][SU]
    __nv_bfloat16* u_lo = (__nv_bfloat16*)(smem_raw + 49920);       // [48][SU]
    __nv_bfloat16* h_hi = (__nv_bfloat16*)(smem_raw + 99840);       // [32][SU]
    __nv_bfloat16* h_lo = (__nv_bfloat16*)(smem_raw + 133120);      // [32][SU]
    float*         red  = (float*)(smem_raw + 166400);              // [4q][3ni][32 lanes][4]
    float*         ghs  = (float*)(smem_raw + 172544);              // [48][33]

    const int bid   = blockIdx.x;     // 0..127
    const int tid   = threadIdx.x;    // 0..255
    const int slice = bid & 31;
    const int bt    = (bid >> 5) & 1;
    const int dir   = bid >> 6;
    const int b0 = bt * 32, u0 = slice * 16;
    const int grp = dir * 2 + bt;
    const float* __restrict__ Uw = dir ? Ub : Uf;

    // one-time: full-K U slice -> bf16 hi/lo. rows o = gate*16 + unit-local
    for (int v = tid; v < 48 * 512; v += 256) {
        int o = v >> 9;
        int k = v & 511;
        float w = Uw[(size_t)k * G3 + (o >> 4) * 512 + u0 + (o & 15)];
        __nv_bfloat16 wh = __float2bfloat16(w);
        u_hi[o * SU + k] = wh;
        u_lo[o * SU + k] = __float2bfloat16(w - __bfloat162float(wh));
    }

    // phase-B ownership: thread -> (batch pb, unit pair pu)
    const int pb = tid >> 3;             // 0..31
    const int pu = 2 * (tid & 7);        // 0..14
    const int bB = b0 + pb;
    const int u  = u0 + pu;              // global unit (even)

    // init H = 0 in parity-0 buffers (own region)
    *(uint32_t*)&g_Hhi[0][dir][bB][u] = 0u;
    *(uint32_t*)&g_Hlo[0][dir][bB][u] = 0u;
    grp_sync(grp, 32);

    // phase-A warp tiling: q = warp&3 -> (m-half, n-trio); kh = warp>>2 -> K half
    const int warp = tid >> 5;
    const int lane = tid & 31;
    const int g    = lane >> 2;
    const int tg   = lane & 3;
    const int q    = warp & 3;
    const int kh   = warp >> 2;
    const int m0w  = (q & 1) * 16;
    const int n0w  = (q >> 1) * 24;
    const int kbase = kh * 256;

    // ldmatrix per-lane row/column addressing (bytes)
    const int arow  = m0w + (lane & 7) + ((lane >> 3) & 1) * 8;   // A x4
    const int akofs = (lane >> 4) * 8;
    const int b4row = n0w + (lane & 7) + ((lane >> 4) << 3);      // B x4 (ni 0,1)
    const int b4kofs = ((lane >> 3) & 1) * 8;
    const int b2row = n0w + 16 + (lane & 7);                      // B x2 (ni 2)
    const int b2kofs = ((lane >> 3) & 1) * 8;

    const uint32_t ahi_b = smem_u32(h_hi) + (uint32_t)(arow * SU + kbase + akofs) * 2;
    const uint32_t alo_b = smem_u32(h_lo) + (uint32_t)(arow * SU + kbase + akofs) * 2;
    const uint32_t b4hi  = smem_u32(u_hi) + (uint32_t)(b4row * SU + kbase + b4kofs) * 2;
    const uint32_t b4lo  = smem_u32(u_lo) + (uint32_t)(b4row * SU + kbase + b4kofs) * 2;
    const uint32_t b2hi  = smem_u32(u_hi) + (uint32_t)(b2row * SU + kbase + b2kofs) * 2;
    const uint32_t b2lo  = smem_u32(u_lo) + (uint32_t)(b2row * SU + kbase + b2kofs) * 2;

    const uint32_t hhi_s = smem_u32(h_hi);
    const uint32_t hlo_s = smem_u32(h_lo);

    const float* __restrict__ brr = (dir ? bb : bf) + G3;
    const float2 bz  = *(const float2*)&brr[u];
    const float2 brc = *(const float2*)&brr[512 + u];
    const float2 bhc = *(const float2*)&brr[1024 + u];

    float2 hold = make_float2(0.f, 0.f);
    float* __restrict__ state = out + (size_t)B_ * T_ * 1024;

    for (int s = 0; s < T_; ++s) {
        const int t  = dir ? (T_ - 1 - s) : s;
        const int rp = s & 1;
        const int wp = rp ^ 1;

        // ---- prefetch phase-B inputs ---------------------------------------
        const bool m = (x[bB * T_ + t] != 0);
        const float* __restrict__ gx = &g_GX[dir][t][bB][0];
        float2 xz = __ldcg((const float2*)&gx[u]);
        float2 xr = __ldcg((const float2*)&gx[512 + u]);
        float2 xh = __ldcg((const float2*)&gx[1024 + u]);

        // ---- stage h: cp.async from hi/lo gmem buffers ----------------------
        for (int j = tid; j < 2048; j += 256) {
            int b  = j >> 6;                  // 0..31
            int kv = (j & 63) * 8;            // 0..504 (bf16 elems, 16B chunks)
            CP_ASYNC16(hhi_s + (uint32_t)(b * SU + kv) * 2, &g_Hhi[rp][dir][b0 + b][kv]);
            CP_ASYNC16(hlo_s + (uint32_t)(b * SU + kv) * 2, &g_Hlo[rp][dir][b0 + b][kv]);
        }
        CP_COMMIT();
        CP_WAIT(0);
        __syncthreads();

        // ---- phase A: gh = h @ Uw (split-bf16, 3 passes, ldmatrix frags) ---
        float acc[3][4];
#pragma unroll
        for (int ni = 0; ni < 3; ++ni)
#pragma unroll
            for (int j = 0; j < 4; ++j) acc[ni][j] = 0.f;

#pragma unroll 4
        for (int k8 = 0; k8 < 16; ++k8) {
            const uint32_t ko = (uint32_t)(k8 * 32);    // 16 bf16 = 32 bytes
            uint32_t ah[4], al[4], b4h[4], b4l[4], b2h[2], b2l[2];
            LDMX4(ah[0], ah[1], ah[2], ah[3], ahi_b + ko);
            LDMX4(al[0], al[1], al[2], al[3], alo_b + ko);
            LDMX4(b4h[0], b4h[1], b4h[2], b4h[3], b4hi + ko);
            LDMX4(b4l[0], b4l[1], b4l[2], b4l[3], b4lo + ko);
            LDMX2(b2h[0], b2h[1], b2hi + ko);
            LDMX2(b2l[0], b2l[1], b2lo + ko);

            mma_bf16(acc[0], ah, b4h[0], b4h[1]);
            mma_bf16(acc[0], al, b4h[0], b4h[1]);
            mma_bf16(acc[0], ah, b4l[0], b4l[1]);
            mma_bf16(acc[1], ah, b4h[2], b4h[3]);
            mma_bf16(acc[1], al, b4h[2], b4h[3]);
            mma_bf16(acc[1], ah, b4l[2], b4l[3]);
            mma_bf16(acc[2], ah, b2h[0], b2h[1]);
            mma_bf16(acc[2], al, b2h[0], b2h[1]);
            mma_bf16(acc[2], ah, b2l[0], b2l[1]);
        }

        // ---- cross-K-half reduction + ghs publish --------------------------
        if (kh == 1) {
#pragma unroll
            for (int ni = 0; ni < 3; ++ni)
                *(float4*)&red[((q * 3 + ni) * 32 + lane) * 4] = *(float4*)acc[ni];
        }
        __syncthreads();
        if (kh == 0) {
#pragma unroll
            for (int ni = 0; ni < 3; ++ni) {
                float4 r = *(const float4*)&red[((q * 3 + ni) * 32 + lane) * 4];
                acc[ni][0] += r.x; acc[ni][1] += r.y;
                acc[ni][2] += r.z; acc[ni][3] += r.w;
                int o = n0w + ni * 8 + 2 * tg;
                ghs[o * 33 + m0w + g]           = acc[ni][0];
                ghs[(o + 1) * 33 + m0w + g]     = acc[ni][1];
                ghs[o * 33 + m0w + g + 8]       = acc[ni][2];
                ghs[(o + 1) * 33 + m0w + g + 8] = acc[ni][3];
            }
        }
        __syncthreads();

        // ---- phase B: block-local gates + H update --------------------------
        {
            float2 gz = make_float2(bz.x  + ghs[pu * 33 + pb],        bz.y  + ghs[(pu + 1) * 33 + pb]);
            float2 gr = make_float2(brc.x + ghs[(16 + pu) * 33 + pb], brc.y + ghs[(17 + pu) * 33 + pb]);
            float2 gh = make_float2(bhc.x + ghs[(32 + pu) * 33 + pb], bhc.y + ghs[(33 + pu) * 33 + pb]);

            float2 hn;
            {
                float z  = __fdividef(1.f, 1.f + __expf(-(xz.x + gz.x)));
                float rr = __fdividef(1.f, 1.f + __expf(-(xr.x + gr.x)));
                float a  = xh.x + rr * gh.x;
                float hc = 1.f - __fdividef(2.f, 1.f + __expf(2.f * a));
                hn.x = z * hold.x + (1.f - z) * hc;
                hn.x = m ? hn.x : hold.x;
            }
            {
                float z  = __fdividef(1.f, 1.f + __expf(-(xz.y + gz.y)));
                float rr = __fdividef(1.f, 1.f + __expf(-(xr.y + gr.y)));
                float a  = xh.y + rr * gh.y;
                float hc = 1.f - __fdividef(2.f, 1.f + __expf(2.f * a));
                hn.y = z * hold.y + (1.f - z) * hc;
                hn.y = m ? hn.y : hold.y;
            }

            hold = hn;
            __nv_bfloat16 hx = __float2bfloat16(hn.x);
            __nv_bfloat16 hy = __float2bfloat16(hn.y);
            uint32_t hi2 = (uint32_t)__bfloat16_as_ushort(hx) |
                           ((uint32_t)__bfloat16_as_ushort(hy) << 16);
            __nv_bfloat16 lx = __float2bfloat16(hn.x - __bfloat162float(hx));
            __nv_bfloat16 ly = __float2bfloat16(hn.y - __bfloat162float(hy));
            uint32_t lo2 = (uint32_t)__bfloat16_as_ushort(lx) |
                           ((uint32_t)__bfloat16_as_ushort(ly) << 16);
            *(uint32_t*)&g_Hhi[wp][dir][bB][u] = hi2;
            *(uint32_t*)&g_Hlo[wp][dir][bB][u] = lo2;
            *(float2*)&out[((size_t)bB * T_ + t) * 1024 + dir * 512 + u] = hn;
            if (s == T_ - 1)
                *(float2*)&state[(size_t)bB * 1024 + dir * 512 + u] = hn;
        }
        grp_sync(grp, 32);   // H writes visible before next step's stage
    }
}

// ======================================================================
// Kernel 3: LayerNorm over last dim (1024) of out, in place
// ======================================================================
__global__ __launch_bounds__(256)
void k_layernorm(float* __restrict__ out,
                 const float* __restrict__ gamma,
                 const float* __restrict__ beta)
{
    const int row = blockIdx.x;
    float* p = out + (size_t)row * 1024;
    const int tid = threadIdx.x;

    float4 v = *(const float4*)&p[tid * 4];
    float s = v.x + v.y + v.z + v.w;
    float q = v.x * v.x + v.y * v.y + v.z * v.z + v.w * v.w;
#pragma unroll
    for (int o = 16; o; o >>= 1) {
        s += __shfl_xor_sync(0xFFFFFFFFu, s, o);
        q += __shfl_xor_sync(0xFFFFFFFFu, q, o);
    }
    __shared__ float ss[8], qq[8];
    __shared__ float mean_s, rstd_s;
    if ((tid & 31) == 0) { ss[tid >> 5] = s; qq[tid >> 5] = q; }
    __syncthreads();
    if (tid == 0) {
        float S = 0.f, Q = 0.f;
#pragma unroll
        for (int i = 0; i < 8; ++i) { S += ss[i]; Q += qq[i]; }
        float mean = S * (1.f / 1024.f);
        float var  = Q * (1.f / 1024.f) - mean * mean;
        mean_s = mean;
        rstd_s = rsqrtf(var + 1e-3f);
    }
    __syncthreads();
    float mean = mean_s, rstd = rstd_s;
    float4 g  = *(const float4*)&gamma[tid * 4];
    float4 be = *(const float4*)&beta[tid * 4];
    v.x = (v.x - mean) * rstd * g.x + be.x;
    v.y = (v.y - mean) * rstd * g.y + be.y;
    v.z = (v.z - mean) * rstd * g.z + be.z;
    v.w = (v.w - mean) * rstd * g.w + be.w;
    *(float4*)&p[tid * 4] = v;
}

// ======================================================================
extern "C" void kernel_launch(void* const* d_in, const int* in_sizes, int n_in,
                              void* d_out, int out_size)
{
    const int*   x     = (const int*)  d_in[0];
    const float* emb   = (const float*)d_in[1];
    const float* Wf    = (const float*)d_in[2];
    const float* Uf    = (const float*)d_in[3];
    const float* bf    = (const float*)d_in[4];
    const float* Wb    = (const float*)d_in[5];
    const float* Ub    = (const float*)d_in[6];
    const float* bb    = (const float*)d_in[7];
    const float* gamma = (const float*)d_in[8];
    const float* beta  = (const float*)d_in[9];
    float* out = (float*)d_out;

    const int smem1 = 2 * (4608 + 4224) * 4;                 // 70656 B
    const int smem2 = 166400 + 6144 + 48 * 33 * 4;           // 178880 B
    cudaFuncSetAttribute(k_input_gemm_mma, cudaFuncAttributeMaxDynamicSharedMemorySize, smem1);
    cudaFuncSetAttribute(k_recurrence, cudaFuncAttributeMaxDynamicSharedMemorySize, smem2);

    k_round<<<1024, 256>>>(emb, Wf, Wb);
    dim3 g1(G3 / 128, (T_ * B_) / 128, 2);
    k_input_gemm_mma<<<g1, 256, smem1>>>(x, bf, bb);
    k_recurrence<<<128, 256, smem2>>>(x, Uf, Ub, bf, bb, out);
    k_layernorm<<<B_ * T_, 256>>>(out, gamma, beta);
}

// round 17
// speedup vs baseline: 1.6163x; 1.1324x over previous
#include <cuda_runtime.h>
#include <cuda_bf16.h>
#include <cuda_fp16.h>
#include <math.h>
#include <stdint.h>

#define B_   64
#define T_   256
#define D_   512
#define U_   512
#define G3   1536   // 3*U
#define V_   32000
#define SU   520    // smem k-stride (fp16 elems): row pitch 1040B -> conflict-free, 16B-aligned

// ---------------- device scratch (static: no runtime allocation) ----------
__device__ float   g_GX[2][T_][B_][G3];      // e@W + b_in, per direction
__device__ __half  g_Hh[2][2][B_][U_];       // H as fp16, double-buffered by parity
__device__ float   g_embr[(size_t)V_ * D_];  // tf32-rounded embedding
__device__ float   g_Wr[2][D_ * G3];         // tf32-rounded W (fwd/bwd)

// per-(dir,bt) barrier state, padded to separate cache lines
struct __align__(128) BarState { unsigned int count; unsigned int gen; unsigned int pad[30]; };
__device__ BarState g_bar[4];

// ---------------- helpers --------------------------------------------------
__device__ __forceinline__ float to_tf32(float v) {
    uint32_t u;
    asm("cvt.rna.tf32.f32 %0, %1;" : "=r"(u) : "f"(v));
    return __uint_as_float(u);
}
__device__ __forceinline__ void mma_f16(float* c, const uint32_t* a, uint32_t b0, uint32_t b1) {
    asm volatile(
        "mma.sync.aligned.m16n8k16.row.col.f32.f16.f16.f32 "
        "{%0,%1,%2,%3}, {%4,%5,%6,%7}, {%8,%9}, {%0,%1,%2,%3};"
        : "+f"(c[0]), "+f"(c[1]), "+f"(c[2]), "+f"(c[3])
        : "r"(a[0]), "r"(a[1]), "r"(a[2]), "r"(a[3]), "r"(b0), "r"(b1));
}
__device__ __forceinline__ uint32_t smem_u32(const void* p) {
    uint32_t a;
    asm("{ .reg .u64 t; cvta.to.shared.u64 t, %1; cvt.u32.u64 %0, t; }" : "=r"(a) : "l"(p));
    return a;
}
#define LDMX4(r0, r1, r2, r3, addr) \
    asm volatile("ldmatrix.sync.aligned.m8n8.x4.shared.b16 {%0,%1,%2,%3}, [%4];" \
                 : "=r"(r0), "=r"(r1), "=r"(r2), "=r"(r3) : "r"(addr))
#define LDMX2(r0, r1, addr) \
    asm volatile("ldmatrix.sync.aligned.m8n8.x2.shared.b16 {%0,%1}, [%2];" \
                 : "=r"(r0), "=r"(r1) : "r"(addr))
#define CP_ASYNC16(dst_u32, src) \
    asm volatile("cp.async.cg.shared.global [%0], [%1], 16;" :: "r"(dst_u32), "l"(src))
#define CP_COMMIT() asm volatile("cp.async.commit_group;" ::: "memory")
#define CP_WAIT(n)  asm volatile("cp.async.wait_group %0;" :: "n"(n) : "memory")

// ---------------- software barrier over one (dir,bt) group's 32 blocks ----
__device__ __forceinline__ void grp_sync(int grp, unsigned nb) {
    volatile unsigned* vgen = (volatile unsigned*)&g_bar[grp].gen;
    __syncthreads();
    if (threadIdx.x == 0) {
        unsigned gen = *vgen;
        __threadfence();                       // order gen-read & prior stores before arrive
        if (atomicAdd(&g_bar[grp].count, 1u) == nb - 1u) {
            g_bar[grp].count = 0u;
            __threadfence();
            atomicAdd(&g_bar[grp].gen, 1u);
        } else {
            while (*vgen == gen) { }
        }
        __threadfence();                       // acquire
    }
    __syncthreads();
}

// ======================================================================
// Kernel 0: round emb / Wf / Wb to tf32 (rna) into static buffers.
// ======================================================================
__global__ __launch_bounds__(256)
void k_round(const float* __restrict__ emb,
             const float* __restrict__ Wf,
             const float* __restrict__ Wb)
{
    const size_t stride = (size_t)gridDim.x * blockDim.x;
    const size_t i0 = (size_t)blockIdx.x * blockDim.x + threadIdx.x;
    const size_t n_emb4 = (size_t)V_ * D_ / 4;
    const size_t n_w4   = (size_t)D_ * G3 / 4;

    for (size_t i = i0; i < n_emb4; i += stride) {
        float4 v = ((const float4*)emb)[i];
        v.x = to_tf32(v.x); v.y = to_tf32(v.y); v.z = to_tf32(v.z); v.w = to_tf32(v.w);
        ((float4*)g_embr)[i] = v;
    }
    for (size_t i = i0; i < n_w4; i += stride) {
        float4 a = ((const float4*)Wf)[i];
        a.x = to_tf32(a.x); a.y = to_tf32(a.y); a.z = to_tf32(a.z); a.w = to_tf32(a.w);
        ((float4*)g_Wr[0])[i] = a;
        float4 b = ((const float4*)Wb)[i];
        b.x = to_tf32(b.x); b.y = to_tf32(b.y); b.z = to_tf32(b.z); b.w = to_tf32(b.w);
        ((float4*)g_Wr[1])[i] = b;
    }
}

// ======================================================================
// Kernel 1 (mma.sync tf32, cp.async double-buffered) — R14/R16, proven.
// ======================================================================
__global__ __launch_bounds__(256, 2)
void k_input_gemm_mma(const int* __restrict__ x,
                      const float* __restrict__ bf,
                      const float* __restrict__ bb)
{
    extern __shared__ float smem_k1[];
    float* Asb[2] = { smem_k1, smem_k1 + 4608 };
    float* Bsb[2] = { smem_k1 + 9216, smem_k1 + 9216 + 4224 };
    __shared__ int tok[128];

    const int jt  = blockIdx.x;     // 0..11
    const int mt  = blockIdx.y;     // 0..127
    const int dir = blockIdx.z;
    const float* __restrict__ W   = dir ? g_Wr[1] : g_Wr[0];
    const float* __restrict__ bin = dir ? bb : bf;
    const int j0 = jt * 128;
    const int m0 = mt * 128;

    const int tid  = threadIdx.x;
    const int warp = tid >> 5;
    const int lane = tid & 31;
    const int g    = lane >> 2;
    const int tg   = lane & 3;
    const int wm0  = (warp >> 2) * 64;
    const int wn0  = (warp & 3) * 32;

    if (tid < 128) {
        int m = m0 + tid;
        tok[tid] = x[(m & 63) * T_ + (m >> 6)];
    }
    __syncthreads();

    int ar[4], aq[4], bk[4], bn[4];
#pragma unroll
    for (int it = 0; it < 4; ++it) {
        int i2 = it * 256 + tid;
        ar[it] = i2 >> 3;
        aq[it] = (i2 & 7) * 4;
        bk[it] = i2 >> 5;
        bn[it] = (i2 & 31) * 4;
    }
    uint32_t asu[2] = { smem_u32(Asb[0]), smem_u32(Asb[1]) };
    uint32_t bsu[2] = { smem_u32(Bsb[0]), smem_u32(Bsb[1]) };

    auto issue = [&](int kc, int buf) {
        const int k0 = kc * 32;
#pragma unroll
        for (int it = 0; it < 4; ++it) {
            CP_ASYNC16(asu[buf] + (uint32_t)(ar[it] * 36 + aq[it]) * 4,
                       &g_embr[(size_t)tok[ar[it]] * D_ + k0 + aq[it]]);
            CP_ASYNC16(bsu[buf] + (uint32_t)(bk[it] * 132 + bn[it]) * 4,
                       &W[(size_t)(k0 + bk[it]) * G3 + j0 + bn[it]]);
        }
    };

    float acc[4][4][4];
#pragma unroll
    for (int mi = 0; mi < 4; ++mi)
#pragma unroll
        for (int ni = 0; ni < 4; ++ni)
#pragma unroll
            for (int q = 0; q < 4; ++q) acc[mi][ni][q] = 0.f;

    issue(0, 0);
    CP_COMMIT();

    for (int kc = 0; kc < 16; ++kc) {
        if (kc < 15) { issue(kc + 1, (kc + 1) & 1); CP_COMMIT(); }
        if (kc < 15) { CP_WAIT(1); } else { CP_WAIT(0); }
        __syncthreads();

        const float* As = Asb[kc & 1];
        const float* Bs = Bsb[kc & 1];
#pragma unroll
        for (int k8 = 0; k8 < 4; ++k8) {
            const int kk = k8 * 8;
            uint32_t bfr[4][2];
#pragma unroll
            for (int ni = 0; ni < 4; ++ni) {
                int n = wn0 + ni * 8 + g;
                bfr[ni][0] = __float_as_uint(Bs[(kk + tg) * 132 + n]);
                bfr[ni][1] = __float_as_uint(Bs[(kk + tg + 4) * 132 + n]);
            }
#pragma unroll
            for (int mi = 0; mi < 4; ++mi) {
                int mr = wm0 + mi * 16 + g;
                uint32_t afr[4];
                afr[0] = __float_as_uint(As[mr * 36 + kk + tg]);
                afr[1] = __float_as_uint(As[(mr + 8) * 36 + kk + tg]);
                afr[2] = __float_as_uint(As[mr * 36 + kk + tg + 4]);
                afr[3] = __float_as_uint(As[(mr + 8) * 36 + kk + tg + 4]);
#pragma unroll
                for (int ni = 0; ni < 4; ++ni) {
                    asm volatile(
                        "mma.sync.aligned.m16n8k8.row.col.f32.tf32.tf32.f32 "
                        "{%0,%1,%2,%3}, {%4,%5,%6,%7}, {%8,%9}, {%0,%1,%2,%3};"
                        : "+f"(acc[mi][ni][0]), "+f"(acc[mi][ni][1]),
                          "+f"(acc[mi][ni][2]), "+f"(acc[mi][ni][3])
                        : "r"(afr[0]), "r"(afr[1]), "r"(afr[2]), "r"(afr[3]),
                          "r"(bfr[ni][0]), "r"(bfr[ni][1]));
                }
            }
        }
        __syncthreads();
    }

#pragma unroll
    for (int mi = 0; mi < 4; ++mi) {
        int m_lo = m0 + wm0 + mi * 16 + g;
        int m_hi = m_lo + 8;
#pragma unroll
        for (int ni = 0; ni < 4; ++ni) {
            int c = j0 + wn0 + ni * 8 + 2 * tg;
            float2 bi = *(const float2*)&bin[c];
            float2 v0 = make_float2(acc[mi][ni][0] + bi.x, acc[mi][ni][1] + bi.y);
            float2 v1 = make_float2(acc[mi][ni][2] + bi.x, acc[mi][ni][3] + bi.y);
            *(float2*)&g_GX[dir][m_lo >> 6][m_lo & 63][c] = v0;
            *(float2*)&g_GX[dir][m_hi >> 6][m_hi & 63][c] = v1;
        }
    }
}

// ======================================================================
// Kernel 2: persistent bidirectional GRU recurrence — ONE barrier per step.
// This round: fp16 operands, h UNSPLIT (single fp16), U split fp16 hi/lo.
// Phase A = 2 mma passes: a·U_hi + a·U_lo (96 HMMA/warp/step, was 144).
// ======================================================================
__global__ __launch_bounds__(256, 1)
void k_recurrence(const int* __restrict__ x,
                  const float* __restrict__ Uf,
                  const float* __restrict__ Ub,
                  const float* __restrict__ bf,
                  const float* __restrict__ bb,
                  float* __restrict__ out)
{
    extern __shared__ char smem_raw[];
    __half* u_hi = (__half*)smem_raw;                 // [48][SU]
    __half* u_lo = (__half*)(smem_raw + 49920);       // [48][SU]
    __half* h_s  = (__half*)(smem_raw + 99840);       // [32][SU]
    float*  red  = (float*)(smem_raw + 133120);       // [4q][3ni][32 lanes][4]
    float*  ghs  = (float*)(smem_raw + 139264);       // [48][33]

    const int bid   = blockIdx.x;     // 0..127
    const int tid   = threadIdx.x;    // 0..255
    const int slice = bid & 31;
    const int bt    = (bid >> 5) & 1;
    const int dir   = bid >> 6;
    const int b0 = bt * 32, u0 = slice * 16;
    const int grp = dir * 2 + bt;
    const float* __restrict__ Uw = dir ? Ub : Uf;

    // one-time: full-K U slice -> fp16 hi/lo. rows o = gate*16 + unit-local
    for (int v = tid; v < 48 * 512; v += 256) {
        int o = v >> 9;
        int k = v & 511;
        float w = Uw[(size_t)k * G3 + (o >> 4) * 512 + u0 + (o & 15)];
        __half wh = __float2half(w);
        u_hi[o * SU + k] = wh;
        u_lo[o * SU + k] = __float2half(w - __half2float(wh));
    }

    // phase-B ownership: thread -> (batch pb, unit pair pu)
    const int pb = tid >> 3;             // 0..31
    const int pu = 2 * (tid & 7);        // 0..14
    const int bB = b0 + pb;
    const int u  = u0 + pu;              // global unit (even)

    // init H = 0 in parity-0 buffer (own region)
    *(uint32_t*)&g_Hh[0][dir][bB][u] = 0u;
    grp_sync(grp, 32);

    // phase-A warp tiling: q = warp&3 -> (m-half, n-trio); kh = warp>>2 -> K half
    const int warp = tid >> 5;
    const int lane = tid & 31;
    const int g    = lane >> 2;
    const int tg   = lane & 3;
    const int q    = warp & 3;
    const int kh   = warp >> 2;
    const int m0w  = (q & 1) * 16;
    const int n0w  = (q >> 1) * 24;
    const int kbase = kh * 256;

    // ldmatrix per-lane row/column addressing (fp16 elems; b16 layout identical)
    const int arow  = m0w + (lane & 7) + ((lane >> 3) & 1) * 8;   // A x4
    const int akofs = (lane >> 4) * 8;
    const int b4row = n0w + (lane & 7) + ((lane >> 4) << 3);      // B x4 (ni 0,1)
    const int b4kofs = ((lane >> 3) & 1) * 8;
    const int b2row = n0w + 16 + (lane & 7);                      // B x2 (ni 2)
    const int b2kofs = ((lane >> 3) & 1) * 8;

    const uint32_t a_b  = smem_u32(h_s)  + (uint32_t)(arow * SU + kbase + akofs) * 2;
    const uint32_t b4hi = smem_u32(u_hi) + (uint32_t)(b4row * SU + kbase + b4kofs) * 2;
    const uint32_t b4lo = smem_u32(u_lo) + (uint32_t)(b4row * SU + kbase + b4kofs) * 2;
    const uint32_t b2hi = smem_u32(u_hi) + (uint32_t)(b2row * SU + kbase + b2kofs) * 2;
    const uint32_t b2lo = smem_u32(u_lo) + (uint32_t)(b2row * SU + kbase + b2kofs) * 2;

    const uint32_t hs_s = smem_u32(h_s);

    const float* __restrict__ brr = (dir ? bb : bf) + G3;
    const float2 bz  = *(const float2*)&brr[u];
    const float2 brc = *(const float2*)&brr[512 + u];
    const float2 bhc = *(const float2*)&brr[1024 + u];

    float2 hold = make_float2(0.f, 0.f);
    float* __restrict__ state = out + (size_t)B_ * T_ * 1024;

    for (int s = 0; s < T_; ++s) {
        const int t  = dir ? (T_ - 1 - s) : s;
        const int rp = s & 1;
        const int wp = rp ^ 1;

        // ---- prefetch phase-B inputs ---------------------------------------
        const bool m = (x[bB * T_ + t] != 0);
        const float* __restrict__ gx = &g_GX[dir][t][bB][0];
        float2 xz = __ldcg((const float2*)&gx[u]);
        float2 xr = __ldcg((const float2*)&gx[512 + u]);
        float2 xh = __ldcg((const float2*)&gx[1024 + u]);

        // ---- stage h: cp.async from fp16 gmem buffer (32KB) -----------------
        for (int j = tid; j < 2048; j += 256) {
            int b  = j >> 6;                  // 0..31
            int kv = (j & 63) * 8;            // 0..504 (fp16 elems, 16B chunks)
            CP_ASYNC16(hs_s + (uint32_t)(b * SU + kv) * 2, &g_Hh[rp][dir][b0 + b][kv]);
        }
        CP_COMMIT();
        CP_WAIT(0);
        __syncthreads();

        // ---- phase A: gh = h @ (U_hi + U_lo), 2 fp16 mma passes -------------
        float acc[3][4];
#pragma unroll
        for (int ni = 0; ni < 3; ++ni)
#pragma unroll
            for (int j = 0; j < 4; ++j) acc[ni][j] = 0.f;

#pragma unroll 4
        for (int k8 = 0; k8 < 16; ++k8) {
            const uint32_t ko = (uint32_t)(k8 * 32);    // 16 fp16 = 32 bytes
            uint32_t a[4], b4h[4], b4l[4], b2h[2], b2l[2];
            LDMX4(a[0], a[1], a[2], a[3], a_b + ko);
            LDMX4(b4h[0], b4h[1], b4h[2], b4h[3], b4hi + ko);
            LDMX4(b4l[0], b4l[1], b4l[2], b4l[3], b4lo + ko);
            LDMX2(b2h[0], b2h[1], b2hi + ko);
            LDMX2(b2l[0], b2l[1], b2lo + ko);

            mma_f16(acc[0], a, b4h[0], b4h[1]);
            mma_f16(acc[0], a, b4l[0], b4l[1]);
            mma_f16(acc[1], a, b4h[2], b4h[3]);
            mma_f16(acc[1], a, b4l[2], b4l[3]);
            mma_f16(acc[2], a, b2h[0], b2h[1]);
            mma_f16(acc[2], a, b2l[0], b2l[1]);
        }

        // ---- cross-K-half reduction + ghs publish --------------------------
        if (kh == 1) {
#pragma unroll
            for (int ni = 0; ni < 3; ++ni)
                *(float4*)&red[((q * 3 + ni) * 32 + lane) * 4] = *(float4*)acc[ni];
        }
        __syncthreads();
        if (kh == 0) {
#pragma unroll
            for (int ni = 0; ni < 3; ++ni) {
                float4 r = *(const float4*)&red[((q * 3 + ni) * 32 + lane) * 4];
                acc[ni][0] += r.x; acc[ni][1] += r.y;
                acc[ni][2] += r.z; acc[ni][3] += r.w;
                int o = n0w + ni * 8 + 2 * tg;
                ghs[o * 33 + m0w + g]           = acc[ni][0];
                ghs[(o + 1) * 33 + m0w + g]     = acc[ni][1];
                ghs[o * 33 + m0w + g + 8]       = acc[ni][2];
                ghs[(o + 1) * 33 + m0w + g + 8] = acc[ni][3];
            }
        }
        __syncthreads();

        // ---- phase B: block-local gates + H update --------------------------
        {
            float2 gz = make_float2(bz.x  + ghs[pu * 33 + pb],        bz.y  + ghs[(pu + 1) * 33 + pb]);
            float2 gr = make_float2(brc.x + ghs[(16 + pu) * 33 + pb], brc.y + ghs[(17 + pu) * 33 + pb]);
            float2 gh = make_float2(bhc.x + ghs[(32 + pu) * 33 + pb], bhc.y + ghs[(33 + pu) * 33 + pb]);

            float2 hn;
            {
                float z  = __fdividef(1.f, 1.f + __expf(-(xz.x + gz.x)));
                float rr = __fdividef(1.f, 1.f + __expf(-(xr.x + gr.x)));
                float a  = xh.x + rr * gh.x;
                float hc = 1.f - __fdividef(2.f, 1.f + __expf(2.f * a));
                hn.x = z * hold.x + (1.f - z) * hc;
                hn.x = m ? hn.x : hold.x;
            }
            {
                float z  = __fdividef(1.f, 1.f + __expf(-(xz.y + gz.y)));
                float rr = __fdividef(1.f, 1.f + __expf(-(xr.y + gr.y)));
                float a  = xh.y + rr * gh.y;
                float hc = 1.f - __fdividef(2.f, 1.f + __expf(2.f * a));
                hn.y = z * hold.y + (1.f - z) * hc;
                hn.y = m ? hn.y : hold.y;
            }

            hold = hn;
            __half hx = __float2half(hn.x);
            __half hy = __float2half(hn.y);
            uint32_t p2 = (uint32_t)__half_as_ushort(hx) |
                          ((uint32_t)__half_as_ushort(hy) << 16);
            *(uint32_t*)&g_Hh[wp][dir][bB][u] = p2;
            *(float2*)&out[((size_t)bB * T_ + t) * 1024 + dir * 512 + u] = hn;
            if (s == T_ - 1)
                *(float2*)&state[(size_t)bB * 1024 + dir * 512 + u] = hn;
        }
        grp_sync(grp, 32);   // H writes visible before next step's stage
    }
}

// ======================================================================
// Kernel 3: LayerNorm over last dim (1024) of out, in place
// ======================================================================
__global__ __launch_bounds__(256)
void k_layernorm(float* __restrict__ out,
                 const float* __restrict__ gamma,
                 const float* __restrict__ beta)
{
    const int row = blockIdx.x;
    float* p = out + (size_t)row * 1024;
    const int tid = threadIdx.x;

    float4 v = *(const float4*)&p[tid * 4];
    float s = v.x + v.y + v.z + v.w;
    float q = v.x * v.x + v.y * v.y + v.z * v.z + v.w * v.w;
#pragma unroll
    for (int o = 16; o; o >>= 1) {
        s += __shfl_xor_sync(0xFFFFFFFFu, s, o);
        q += __shfl_xor_sync(0xFFFFFFFFu, q, o);
    }
    __shared__ float ss[8], qq[8];
    __shared__ float mean_s, rstd_s;
    if ((tid & 31) == 0) { ss[tid >> 5] = s; qq[tid >> 5] = q; }
    __syncthreads();
    if (tid == 0) {
        float S = 0.f, Q = 0.f;
#pragma unroll
        for (int i = 0; i < 8; ++i) { S += ss[i]; Q += qq[i]; }
        float mean = S * (1.f / 1024.f);
        float var  = Q * (1.f / 1024.f) - mean * mean;
        mean_s = mean;
        rstd_s = rsqrtf(var + 1e-3f);
    }
    __syncthreads();
    float mean = mean_s, rstd = rstd_s;
    float4 g  = *(const float4*)&gamma[tid * 4];
    float4 be = *(const float4*)&beta[tid * 4];
    v.x = (v.x - mean) * rstd * g.x + be.x;
    v.y = (v.y - mean) * rstd * g.y + be.y;
    v.z = (v.z - mean) * rstd * g.z + be.z;
    v.w = (v.w - mean) * rstd * g.w + be.w;
    *(float4*)&p[tid * 4] = v;
}

// ======================================================================
extern "C" void kernel_launch(void* const* d_in, const int* in_sizes, int n_in,
                              void* d_out, int out_size)
{
    const int*   x     = (const int*)  d_in[0];
    const float* emb   = (const float*)d_in[1];
    const float* Wf    = (const float*)d_in[2];
    const float* Uf    = (const float*)d_in[3];
    const float* bf    = (const float*)d_in[4];
    const float* Wb    = (const float*)d_in[5];
    const float* Ub    = (const float*)d_in[6];
    const float* bb    = (const float*)d_in[7];
    const float* gamma = (const float*)d_in[8];
    const float* beta  = (const float*)d_in[9];
    float* out = (float*)d_out;

    const int smem1 = 2 * (4608 + 4224) * 4;                 // 70656 B
    const int smem2 = 49920 * 2 + 33280 + 6144 + 48 * 33 * 4; // 145600 B
    cudaFuncSetAttribute(k_input_gemm_mma, cudaFuncAttributeMaxDynamicSharedMemorySize, smem1);
    cudaFuncSetAttribute(k_recurrence, cudaFuncAttributeMaxDynamicSharedMemorySize, smem2);

    k_round<<<1024, 256>>>(emb, Wf, Wb);
    dim3 g1(G3 / 128, (T_ * B_) / 128, 2);
    k_input_gemm_mma<<<g1, 256, smem1>>>(x, bf, bb);
    k_recurrence<<<128, 256, smem2>>>(x, Uf, Ub, bf, bb, out);
    k_layernorm<<<B_ * T_, 256>>>(out, gamma, beta);
}